// round 1
// baseline (speedup 1.0000x reference)
#include <cuda_runtime.h>
#include <cstddef>

// Problem-size constants (match reference setup_inputs)
#define NP_C 200000
#define NU_C 50000
#define E_C  2000000
#define OUTF 16

// ---------------- device scratch (BSS, no allocation) ----------------
__device__ int   g_deg[NP_C];          // reused per edge type (sequential builds)
__device__ int   g_cur[NP_C];          // scatter cursor, reused
__device__ int   g_part[256];          // scan partials, reused
__device__ int   g_rp_v[NU_C + 1];
__device__ int   g_rp_r[NP_C + 1];
__device__ int   g_rp_c[NP_C + 1];
__device__ int   g_ce_v[E_C];
__device__ int   g_ce_r[E_C];
__device__ int   g_ce_c[E_C];
__device__ float g_b0[NP_C * OUTF];    // transform buffers (P-sized covers U)
__device__ float g_b1[NP_C * OUTF];
__device__ float g_b2[NP_C * OUTF];
__device__ float g_p1[NP_C * OUTF];    // layer-1 activations
__device__ float g_u1[NU_C * OUTF];

// ---------------- CSR build kernels ----------------
__global__ void count_kernel(const int* __restrict__ dst, int e, int* __restrict__ deg) {
    int i = blockIdx.x * blockDim.x + threadIdx.x;
    if (i < e) atomicAdd(&deg[dst[i]], 1);
}

__global__ void scan_block_sums(const int* __restrict__ deg, int n, int* __restrict__ part) {
    __shared__ int s[1024];
    int tid = threadIdx.x;
    int i = blockIdx.x * 1024 + tid;
    s[tid] = (i < n) ? deg[i] : 0;
    __syncthreads();
    #pragma unroll
    for (int o = 512; o > 0; o >>= 1) {
        if (tid < o) s[tid] += s[tid + o];
        __syncthreads();
    }
    if (tid == 0) part[blockIdx.x] = s[0];
}

__global__ void scan_top(int* __restrict__ part, int nb) {
    __shared__ int s[256];
    int tid = threadIdx.x;
    int v = (tid < nb) ? part[tid] : 0;
    s[tid] = v;
    __syncthreads();
    #pragma unroll
    for (int o = 1; o < 256; o <<= 1) {
        int t = (tid >= o) ? s[tid - o] : 0;
        __syncthreads();
        s[tid] += t;
        __syncthreads();
    }
    if (tid < nb) part[tid] = s[tid] - v;   // exclusive
}

__global__ void scan_final(const int* __restrict__ deg, int n,
                           const int* __restrict__ part,
                           int* __restrict__ rp, int* __restrict__ cur) {
    __shared__ int s[1024];
    int tid = threadIdx.x;
    int i = blockIdx.x * 1024 + tid;
    int v = (i < n) ? deg[i] : 0;
    s[tid] = v;
    __syncthreads();
    #pragma unroll
    for (int o = 1; o < 1024; o <<= 1) {
        int t = (tid >= o) ? s[tid - o] : 0;
        __syncthreads();
        s[tid] += t;
        __syncthreads();
    }
    if (i < n) {
        int incl = part[blockIdx.x] + s[tid];   // inclusive prefix
        rp[i + 1] = incl;
        cur[i] = incl - v;                      // exclusive = row start
        if (i == 0) rp[0] = 0;
    }
}

__global__ void scatter_kernel(const int* __restrict__ src, const int* __restrict__ dst,
                               int e, int* __restrict__ cur, int* __restrict__ ce) {
    int i = blockIdx.x * blockDim.x + threadIdx.x;
    if (i < e) {
        int p = atomicAdd(&cur[dst[i]], 1);
        ce[p] = src[i];
    }
}

// ---------------- node transform: out[n,16] = x[n,F] @ (Wa [+Wb]) [+ba+bb] ----------------
template <int F>
__global__ void __launch_bounds__(256)
transform_kernel(const float* __restrict__ x, int n,
                 const float* __restrict__ Wa, const float* __restrict__ Wb,
                 const float* __restrict__ ba, const float* __restrict__ bb,
                 float* __restrict__ out) {
    __shared__ float Ws[F * 16];
    __shared__ float bs[16];
    int tid = threadIdx.x;
    for (int i = tid; i < F * 16; i += blockDim.x) {
        float w = Wa[i];
        if (Wb) w += Wb[i];
        Ws[i] = w;
    }
    if (tid < 16) {
        float b = 0.f;
        if (ba) b += ba[tid];
        if (bb) b += bb[tid];
        bs[tid] = b;
    }
    __syncthreads();
    int r = blockIdx.x * blockDim.x + tid;
    if (r >= n) return;
    float acc[16];
    #pragma unroll
    for (int c = 0; c < 16; c++) acc[c] = bs[c];
    const float4* xr = reinterpret_cast<const float4*>(x + (size_t)r * F);
    #pragma unroll
    for (int k4 = 0; k4 < F / 4; k4++) {
        float4 v = __ldg(&xr[k4]);
        #pragma unroll
        for (int c = 0; c < 16; c++) {
            acc[c] = fmaf(v.x, Ws[(4 * k4 + 0) * 16 + c], acc[c]);
            acc[c] = fmaf(v.y, Ws[(4 * k4 + 1) * 16 + c], acc[c]);
            acc[c] = fmaf(v.z, Ws[(4 * k4 + 2) * 16 + c], acc[c]);
            acc[c] = fmaf(v.w, Ws[(4 * k4 + 3) * 16 + c], acc[c]);
        }
    }
    float4* o = reinterpret_cast<float4*>(out + (size_t)r * 16);
    o[0] = make_float4(acc[0], acc[1], acc[2], acc[3]);
    o[1] = make_float4(acc[4], acc[5], acc[6], acc[7]);
    o[2] = make_float4(acc[8], acc[9], acc[10], acc[11]);
    o[3] = make_float4(acc[12], acc[13], acc[14], acc[15]);
}

// ---------------- gather kernels: warp per dst node, 16 lanes = 16 dims, 2 halves split edges ----------------
__global__ void __launch_bounds__(256)
gather1_kernel(const int* __restrict__ rp, const int* __restrict__ ce,
               const float* __restrict__ tsrc, const float* __restrict__ tself,
               float* __restrict__ out, int n) {
    int w = (blockIdx.x * blockDim.x + threadIdx.x) >> 5;
    if (w >= n) return;
    int lane = threadIdx.x & 31;
    int d = lane & 15;
    int half = lane >> 4;
    int beg = __ldg(&rp[w]), end = __ldg(&rp[w + 1]);
    float acc = 0.f;
    int e = beg + half;
    for (; e + 2 < end; e += 4) {
        int s0 = __ldg(&ce[e]);
        int s1 = __ldg(&ce[e + 2]);
        float v0 = __ldg(&tsrc[(size_t)s0 * 16 + d]);
        float v1 = __ldg(&tsrc[(size_t)s1 * 16 + d]);
        acc += v0 + v1;
    }
    if (e < end) acc += __ldg(&tsrc[(size_t)__ldg(&ce[e]) * 16 + d]);
    acc += __shfl_xor_sync(0xffffffffu, acc, 16);
    int deg = end - beg;
    float inv = deg > 0 ? (1.0f / (float)deg) : 0.f;
    float v = fmaf(acc, inv, __ldg(&tself[(size_t)w * 16 + d]));
    if (half == 0) out[(size_t)w * 16 + d] = fmaxf(v, 0.f);
}

__global__ void __launch_bounds__(256)
gather2_kernel(const int* __restrict__ rpA, const int* __restrict__ ceA, const float* __restrict__ tA,
               const int* __restrict__ rpB, const int* __restrict__ ceB, const float* __restrict__ tB,
               const float* __restrict__ tself, float* __restrict__ out, int n) {
    int w = (blockIdx.x * blockDim.x + threadIdx.x) >> 5;
    if (w >= n) return;
    int lane = threadIdx.x & 31;
    int d = lane & 15;
    int half = lane >> 4;

    int begA = __ldg(&rpA[w]), endA = __ldg(&rpA[w + 1]);
    float accA = 0.f;
    int e = begA + half;
    for (; e + 2 < endA; e += 4) {
        int s0 = __ldg(&ceA[e]);
        int s1 = __ldg(&ceA[e + 2]);
        accA += __ldg(&tA[(size_t)s0 * 16 + d]) + __ldg(&tA[(size_t)s1 * 16 + d]);
    }
    if (e < endA) accA += __ldg(&tA[(size_t)__ldg(&ceA[e]) * 16 + d]);

    int begB = __ldg(&rpB[w]), endB = __ldg(&rpB[w + 1]);
    float accB = 0.f;
    e = begB + half;
    for (; e + 2 < endB; e += 4) {
        int s0 = __ldg(&ceB[e]);
        int s1 = __ldg(&ceB[e + 2]);
        accB += __ldg(&tB[(size_t)s0 * 16 + d]) + __ldg(&tB[(size_t)s1 * 16 + d]);
    }
    if (e < endB) accB += __ldg(&tB[(size_t)__ldg(&ceB[e]) * 16 + d]);

    accA += __shfl_xor_sync(0xffffffffu, accA, 16);
    accB += __shfl_xor_sync(0xffffffffu, accB, 16);
    int degA = endA - begA, degB = endB - begB;
    float invA = degA > 0 ? (1.0f / (float)degA) : 0.f;
    float invB = degB > 0 ? (1.0f / (float)degB) : 0.f;
    float v = fmaf(accA, invA, fmaf(accB, invB, __ldg(&tself[(size_t)w * 16 + d])));
    if (half == 0) out[(size_t)w * 16 + d] = fmaxf(v, 0.f);
}

// ---------------- host launcher ----------------
static inline void* sym_addr(const void* symbol) {
    void* p = nullptr;
    cudaGetSymbolAddress(&p, symbol);
    return p;
}

extern "C" void kernel_launch(void* const* d_in, const int* in_sizes, int n_in,
                              void* d_out, int out_size) {
    const float* xp = (const float*)d_in[0];
    const float* xu = (const float*)d_in[1];
    const int* ev_src = (const int*)d_in[2];
    const int* ev_dst = (const int*)d_in[3];
    const int* er_src = (const int*)d_in[4];
    const int* er_dst = (const int*)d_in[5];
    const int* ec_src = (const int*)d_in[6];
    const int* ec_dst = (const int*)d_in[7];
    const float* W1v_l = (const float*)d_in[8];
    const float* W1v_r = (const float*)d_in[9];
    const float* b1v   = (const float*)d_in[10];
    const float* W1r_l = (const float*)d_in[11];
    const float* W1r_r = (const float*)d_in[12];
    const float* b1r   = (const float*)d_in[13];
    const float* W1c_l = (const float*)d_in[14];
    const float* W1c_r = (const float*)d_in[15];
    const float* b1c   = (const float*)d_in[16];
    const float* W2v_l = (const float*)d_in[17];
    const float* W2v_r = (const float*)d_in[18];
    const float* b2v   = (const float*)d_in[19];
    const float* W2r_l = (const float*)d_in[20];
    const float* W2r_r = (const float*)d_in[21];
    const float* b2r   = (const float*)d_in[22];
    const float* W2c_l = (const float*)d_in[23];
    const float* W2c_r = (const float*)d_in[24];
    const float* b2c   = (const float*)d_in[25];

    const int NP = in_sizes[0] / 64;
    const int NU = in_sizes[1] / 32;
    const int E  = in_sizes[2];

    int*   deg  = (int*)sym_addr(g_deg);
    int*   cur  = (int*)sym_addr(g_cur);
    int*   part = (int*)sym_addr(g_part);
    int*   rp_v = (int*)sym_addr(g_rp_v);
    int*   rp_r = (int*)sym_addr(g_rp_r);
    int*   rp_c = (int*)sym_addr(g_rp_c);
    int*   ce_v = (int*)sym_addr(g_ce_v);
    int*   ce_r = (int*)sym_addr(g_ce_r);
    int*   ce_c = (int*)sym_addr(g_ce_c);
    float* b0   = (float*)sym_addr(g_b0);
    float* b1   = (float*)sym_addr(g_b1);
    float* b2   = (float*)sym_addr(g_b2);
    float* p1   = (float*)sym_addr(g_p1);
    float* u1   = (float*)sym_addr(g_u1);

    float* out_p = (float*)d_out;               // [NP,16]
    float* out_u = (float*)d_out + (size_t)NP * 16;  // [NU,16]

    const int TB = 256;
    const int eb = (E + TB - 1) / TB;

    // ---- build CSR for the 3 edge types (reused by both layers) ----
    auto build = [&](const int* src, const int* dst, int n, int* rp, int* ce) {
        cudaMemsetAsync(deg, 0, (size_t)n * sizeof(int));
        count_kernel<<<eb, TB>>>(dst, E, deg);
        int nb = (n + 1023) / 1024;
        scan_block_sums<<<nb, 1024>>>(deg, n, part);
        scan_top<<<1, 256>>>(part, nb);
        scan_final<<<nb, 1024>>>(deg, n, part, rp, cur);
        scatter_kernel<<<eb, TB>>>(src, dst, E, cur, ce);
    };
    build(ev_src, ev_dst, NU, rp_v, ce_v);
    build(er_src, er_dst, NP, rp_r, ce_r);
    build(ec_src, ec_dst, NP, rp_c, ce_c);

    auto gblk = [&](int n) { return (n + 7) / 8; };   // warp per node, 256 thr/block

    // ================= layer 1 =================
    // U side: u1 = relu( mean_ev(xp@W1v_l) + b1v + xu@W1v_r )
    transform_kernel<64><<<(NP + TB - 1) / TB, TB>>>(xp, NP, W1v_l, nullptr, nullptr, nullptr, b0);
    transform_kernel<32><<<(NU + TB - 1) / TB, TB>>>(xu, NU, W1v_r, nullptr, b1v, nullptr, b1);
    gather1_kernel<<<gblk(NU), TB>>>(rp_v, ce_v, b0, b1, u1, NU);

    // P side: p1 = relu( mean_er(xu@W1r_l) + mean_ec(xp@W1c_l) + xp@(W1r_r+W1c_r) + b1r+b1c )
    transform_kernel<32><<<(NU + TB - 1) / TB, TB>>>(xu, NU, W1r_l, nullptr, nullptr, nullptr, b0);
    transform_kernel<64><<<(NP + TB - 1) / TB, TB>>>(xp, NP, W1c_l, nullptr, nullptr, nullptr, b1);
    transform_kernel<64><<<(NP + TB - 1) / TB, TB>>>(xp, NP, W1r_r, W1c_r, b1r, b1c, b2);
    gather2_kernel<<<gblk(NP), TB>>>(rp_r, ce_r, b0, rp_c, ce_c, b1, b2, p1, NP);

    // ================= layer 2 =================
    // U side: u2 = relu( mean_ev(p1@W2v_l) + b2v + u1@W2v_r )
    transform_kernel<16><<<(NP + TB - 1) / TB, TB>>>(p1, NP, W2v_l, nullptr, nullptr, nullptr, b0);
    transform_kernel<16><<<(NU + TB - 1) / TB, TB>>>(u1, NU, W2v_r, nullptr, b2v, nullptr, b1);
    gather1_kernel<<<gblk(NU), TB>>>(rp_v, ce_v, b0, b1, out_u, NU);

    // P side: p2 = relu( mean_er(u1@W2r_l) + mean_ec(p1@W2c_l) + p1@(W2r_r+W2c_r) + b2r+b2c )
    transform_kernel<16><<<(NU + TB - 1) / TB, TB>>>(u1, NU, W2r_l, nullptr, nullptr, nullptr, b0);
    transform_kernel<16><<<(NP + TB - 1) / TB, TB>>>(p1, NP, W2c_l, nullptr, nullptr, nullptr, b1);
    transform_kernel<16><<<(NP + TB - 1) / TB, TB>>>(p1, NP, W2r_r, W2c_r, b2r, b2c, b2);
    gather2_kernel<<<gblk(NP), TB>>>(rp_r, ce_r, b0, rp_c, ce_c, b1, b2, out_p, NP);
}

// round 2
// speedup vs baseline: 1.1549x; 1.1549x over previous
#include <cuda_runtime.h>
#include <cstddef>

// Problem-size constants (match reference setup_inputs)
#define NP_C 200000
#define NU_C 50000
#define E_C  2000000
#define OUTF 16

#define NB_U ((NU_C + 1023) / 1024)            // 49
#define NB_P ((NP_C + 1023) / 1024)            // 196
#define NB_TOT (NB_U + NB_P + NB_P)            // 441

// ---------------- device scratch (BSS, no allocation) ----------------
// combined degree/cursor arrays: [0,NU)=v, [NU,NU+NP)=r, [NU+NP,NU+2NP)=c
__device__ int   g_deg3[NU_C + 2 * NP_C];
__device__ int   g_cur3[NU_C + 2 * NP_C];
__device__ int   g_part[3 * 256];
__device__ int   g_rp_v[NU_C + 1];
__device__ int   g_rp_r[NP_C + 1];
__device__ int   g_rp_c[NP_C + 1];
__device__ int   g_ce_v[E_C];
__device__ int   g_ce_r[E_C];
__device__ int   g_ce_c[E_C];
__device__ float g_b0[NP_C * OUTF];    // P-sized transform buffers
__device__ float g_b1[NP_C * OUTF];
__device__ float g_b2[NP_C * OUTF];
__device__ float g_bu0[NU_C * OUTF];   // U-sized transform buffers
__device__ float g_bu1[NU_C * OUTF];
__device__ float g_p1[NP_C * OUTF];    // layer-1 activations
__device__ float g_u1[NU_C * OUTF];

// ---------------- fused CSR build ----------------
__global__ void __launch_bounds__(256)
count3_kernel(const int* __restrict__ dv, const int* __restrict__ dr,
              const int* __restrict__ dc, int e, int* __restrict__ deg3) {
    int i = blockIdx.x * blockDim.x + threadIdx.x;
    if (i >= e) return;
    int a = __ldg(&dv[i]);
    int b = __ldg(&dr[i]);
    int c = __ldg(&dc[i]);
    atomicAdd(&deg3[a], 1);
    atomicAdd(&deg3[NU_C + b], 1);
    atomicAdd(&deg3[NU_C + NP_C + c], 1);
}

__device__ __forceinline__ void seg_decode(int blk, int& seg, int& lb, int& base, int& n) {
    if (blk < NB_U)            { seg = 0; lb = blk;               base = 0;            n = NU_C; }
    else if (blk < NB_U + NB_P){ seg = 1; lb = blk - NB_U;        base = NU_C;         n = NP_C; }
    else                       { seg = 2; lb = blk - NB_U - NB_P; base = NU_C + NP_C;  n = NP_C; }
}

__global__ void scan_bs3(const int* __restrict__ deg3, int* __restrict__ part) {
    __shared__ int s[1024];
    int seg, lb, base, n;
    seg_decode(blockIdx.x, seg, lb, base, n);
    int tid = threadIdx.x;
    int i = lb * 1024 + tid;
    s[tid] = (i < n) ? deg3[base + i] : 0;
    __syncthreads();
    #pragma unroll
    for (int o = 512; o > 0; o >>= 1) {
        if (tid < o) s[tid] += s[tid + o];
        __syncthreads();
    }
    if (tid == 0) part[seg * 256 + lb] = s[0];
}

__global__ void scan_top3(int* __restrict__ part) {
    __shared__ int s[256];
    int seg = blockIdx.x;
    int nb = (seg == 0) ? NB_U : NB_P;
    int tid = threadIdx.x;
    int v = (tid < nb) ? part[seg * 256 + tid] : 0;
    s[tid] = v;
    __syncthreads();
    #pragma unroll
    for (int o = 1; o < 256; o <<= 1) {
        int t = (tid >= o) ? s[tid - o] : 0;
        __syncthreads();
        s[tid] += t;
        __syncthreads();
    }
    if (tid < nb) part[seg * 256 + tid] = s[tid] - v;   // exclusive
}

__global__ void scan_final3(const int* __restrict__ deg3, const int* __restrict__ part,
                            int* __restrict__ rp_v, int* __restrict__ rp_r,
                            int* __restrict__ rp_c, int* __restrict__ cur3) {
    __shared__ int s[1024];
    int seg, lb, base, n;
    seg_decode(blockIdx.x, seg, lb, base, n);
    int* rp = (seg == 0) ? rp_v : (seg == 1) ? rp_r : rp_c;
    int tid = threadIdx.x;
    int i = lb * 1024 + tid;
    int v = (i < n) ? deg3[base + i] : 0;
    s[tid] = v;
    __syncthreads();
    #pragma unroll
    for (int o = 1; o < 1024; o <<= 1) {
        int t = (tid >= o) ? s[tid - o] : 0;
        __syncthreads();
        s[tid] += t;
        __syncthreads();
    }
    if (i < n) {
        int incl = part[seg * 256 + lb] + s[tid];
        rp[i + 1] = incl;
        cur3[base + i] = incl - v;
        if (i == 0) rp[0] = 0;
    }
}

__global__ void __launch_bounds__(256)
scatter3_kernel(const int* __restrict__ sv, const int* __restrict__ dv,
                const int* __restrict__ sr, const int* __restrict__ dr,
                const int* __restrict__ sc, const int* __restrict__ dc,
                int e, int* __restrict__ cur3,
                int* __restrict__ ce_v, int* __restrict__ ce_r, int* __restrict__ ce_c) {
    int i = blockIdx.x * blockDim.x + threadIdx.x;
    if (i >= e) return;
    int s0 = __ldg(&sv[i]); int d0 = __ldg(&dv[i]);
    int s1 = __ldg(&sr[i]); int d1 = __ldg(&dr[i]);
    int s2 = __ldg(&sc[i]); int d2 = __ldg(&dc[i]);
    int p0 = atomicAdd(&cur3[d0], 1);
    int p1 = atomicAdd(&cur3[NU_C + d1], 1);
    int p2 = atomicAdd(&cur3[NU_C + NP_C + d2], 1);
    ce_v[p0] = s0;
    ce_r[p1] = s1;
    ce_c[p2] = s2;
}

// ---------------- fused node transforms: up to 3 weight slots, one input read ----------------
struct TSlots {
    const float* Wa[3];
    const float* Wb[3];
    const float* ba[3];
    const float* bb[3];
    float*       out[3];
};

template <int F, int NS>
__global__ void __launch_bounds__(256)
transform_fused(const float* __restrict__ x, int n, TSlots t) {
    __shared__ float Ws[NS * F * 16];
    __shared__ float bs[NS * 16];
    int tid = threadIdx.x;
    for (int i = tid; i < NS * F * 16; i += blockDim.x) {
        int s = i / (F * 16);
        int j = i % (F * 16);
        float w = t.Wa[s][j];
        if (t.Wb[s]) w += t.Wb[s][j];
        Ws[i] = w;
    }
    if (tid < NS * 16) {
        int s = tid / 16, c = tid % 16;
        float b = 0.f;
        if (t.ba[s]) b += t.ba[s][c];
        if (t.bb[s]) b += t.bb[s][c];
        bs[tid] = b;
    }
    __syncthreads();
    int r = blockIdx.x * blockDim.x + tid;
    if (r >= n) return;
    float acc[NS * 16];
    #pragma unroll
    for (int i = 0; i < NS * 16; i++) acc[i] = bs[i];
    const float4* xr = reinterpret_cast<const float4*>(x + (size_t)r * F);
    #pragma unroll
    for (int k4 = 0; k4 < F / 4; k4++) {
        float4 v = __ldg(&xr[k4]);
        #pragma unroll
        for (int s = 0; s < NS; s++) {
            const float* w0 = &Ws[s * F * 16 + (4 * k4) * 16];
            #pragma unroll
            for (int c = 0; c < 16; c++) {
                float a = acc[s * 16 + c];
                a = fmaf(v.x, w0[c], a);
                a = fmaf(v.y, w0[16 + c], a);
                a = fmaf(v.z, w0[32 + c], a);
                a = fmaf(v.w, w0[48 + c], a);
                acc[s * 16 + c] = a;
            }
        }
    }
    #pragma unroll
    for (int s = 0; s < NS; s++) {
        float4* o = reinterpret_cast<float4*>(t.out[s] + (size_t)r * 16);
        #pragma unroll
        for (int q = 0; q < 4; q++)
            o[q] = make_float4(acc[s * 16 + 4 * q], acc[s * 16 + 4 * q + 1],
                               acc[s * 16 + 4 * q + 2], acc[s * 16 + 4 * q + 3]);
    }
}

// ---------------- gathers: warp per node, 4 lanes per edge row (float4), MLP 16 ----------------
__device__ __forceinline__ void f4add(float4& a, const float4& b) {
    a.x += b.x; a.y += b.y; a.z += b.z; a.w += b.w;
}
__device__ __forceinline__ void f4red_groups(float4& a) {
    #pragma unroll
    for (int m = 4; m <= 16; m <<= 1) {
        a.x += __shfl_xor_sync(0xffffffffu, a.x, m);
        a.y += __shfl_xor_sync(0xffffffffu, a.y, m);
        a.z += __shfl_xor_sync(0xffffffffu, a.z, m);
        a.w += __shfl_xor_sync(0xffffffffu, a.w, m);
    }
}

__device__ __forceinline__ float4 gather_sum(const int* __restrict__ ce,
                                             const float4* __restrict__ tsrc,
                                             int beg, int end, int g, int q) {
    float4 a0 = make_float4(0.f, 0.f, 0.f, 0.f);
    float4 a1 = make_float4(0.f, 0.f, 0.f, 0.f);
    int e = beg + g;
    for (; e + 8 < end; e += 16) {
        int s0 = __ldg(&ce[e]);
        int s1 = __ldg(&ce[e + 8]);
        float4 v0 = __ldg(&tsrc[s0 * 4 + q]);
        float4 v1 = __ldg(&tsrc[s1 * 4 + q]);
        f4add(a0, v0);
        f4add(a1, v1);
    }
    if (e < end) {
        int s0 = __ldg(&ce[e]);
        float4 v0 = __ldg(&tsrc[s0 * 4 + q]);
        f4add(a0, v0);
    }
    f4add(a0, a1);
    return a0;
}

__global__ void __launch_bounds__(256)
gather1_kernel(const int* __restrict__ rp, const int* __restrict__ ce,
               const float4* __restrict__ tsrc, const float4* __restrict__ tself,
               float4* __restrict__ out, int n) {
    int w = (blockIdx.x * blockDim.x + threadIdx.x) >> 5;
    if (w >= n) return;
    int lane = threadIdx.x & 31;
    int g = lane >> 2;          // edge group 0..7
    int q = lane & 3;           // float4 quad within row
    int beg = __ldg(&rp[w]), end = __ldg(&rp[w + 1]);
    float4 acc = gather_sum(ce, tsrc, beg, end, g, q);
    f4red_groups(acc);
    if (lane < 4) {
        int deg = end - beg;
        float inv = deg > 0 ? (1.0f / (float)deg) : 0.f;
        float4 s = __ldg(&tself[w * 4 + q]);
        float4 o;
        o.x = fmaxf(fmaf(acc.x, inv, s.x), 0.f);
        o.y = fmaxf(fmaf(acc.y, inv, s.y), 0.f);
        o.z = fmaxf(fmaf(acc.z, inv, s.z), 0.f);
        o.w = fmaxf(fmaf(acc.w, inv, s.w), 0.f);
        out[w * 4 + q] = o;
    }
}

__global__ void __launch_bounds__(256)
gather2_kernel(const int* __restrict__ rpA, const int* __restrict__ ceA,
               const float4* __restrict__ tA,
               const int* __restrict__ rpB, const int* __restrict__ ceB,
               const float4* __restrict__ tB,
               const float4* __restrict__ tself, float4* __restrict__ out, int n) {
    int w = (blockIdx.x * blockDim.x + threadIdx.x) >> 5;
    if (w >= n) return;
    int lane = threadIdx.x & 31;
    int g = lane >> 2;
    int q = lane & 3;
    int begA = __ldg(&rpA[w]), endA = __ldg(&rpA[w + 1]);
    int begB = __ldg(&rpB[w]), endB = __ldg(&rpB[w + 1]);
    float4 accA = gather_sum(ceA, tA, begA, endA, g, q);
    float4 accB = gather_sum(ceB, tB, begB, endB, g, q);
    f4red_groups(accA);
    f4red_groups(accB);
    if (lane < 4) {
        int degA = endA - begA, degB = endB - begB;
        float invA = degA > 0 ? (1.0f / (float)degA) : 0.f;
        float invB = degB > 0 ? (1.0f / (float)degB) : 0.f;
        float4 s = __ldg(&tself[w * 4 + q]);
        float4 o;
        o.x = fmaxf(fmaf(accA.x, invA, fmaf(accB.x, invB, s.x)), 0.f);
        o.y = fmaxf(fmaf(accA.y, invA, fmaf(accB.y, invB, s.y)), 0.f);
        o.z = fmaxf(fmaf(accA.z, invA, fmaf(accB.z, invB, s.z)), 0.f);
        o.w = fmaxf(fmaf(accA.w, invA, fmaf(accB.w, invB, s.w)), 0.f);
        out[w * 4 + q] = o;
    }
}

// ---------------- host launcher ----------------
static inline void* sym_addr(const void* symbol) {
    void* p = nullptr;
    cudaGetSymbolAddress(&p, symbol);
    return p;
}

extern "C" void kernel_launch(void* const* d_in, const int* in_sizes, int n_in,
                              void* d_out, int out_size) {
    const float* xp = (const float*)d_in[0];
    const float* xu = (const float*)d_in[1];
    const int* ev_src = (const int*)d_in[2];
    const int* ev_dst = (const int*)d_in[3];
    const int* er_src = (const int*)d_in[4];
    const int* er_dst = (const int*)d_in[5];
    const int* ec_src = (const int*)d_in[6];
    const int* ec_dst = (const int*)d_in[7];
    const float* W1v_l = (const float*)d_in[8];
    const float* W1v_r = (const float*)d_in[9];
    const float* b1v   = (const float*)d_in[10];
    const float* W1r_l = (const float*)d_in[11];
    const float* W1r_r = (const float*)d_in[12];
    const float* b1r   = (const float*)d_in[13];
    const float* W1c_l = (const float*)d_in[14];
    const float* W1c_r = (const float*)d_in[15];
    const float* b1c   = (const float*)d_in[16];
    const float* W2v_l = (const float*)d_in[17];
    const float* W2v_r = (const float*)d_in[18];
    const float* b2v   = (const float*)d_in[19];
    const float* W2r_l = (const float*)d_in[20];
    const float* W2r_r = (const float*)d_in[21];
    const float* b2r   = (const float*)d_in[22];
    const float* W2c_l = (const float*)d_in[23];
    const float* W2c_r = (const float*)d_in[24];
    const float* b2c   = (const float*)d_in[25];

    const int NP = NP_C, NU = NU_C, E = E_C;

    int*   deg3 = (int*)sym_addr(g_deg3);
    int*   cur3 = (int*)sym_addr(g_cur3);
    int*   part = (int*)sym_addr(g_part);
    int*   rp_v = (int*)sym_addr(g_rp_v);
    int*   rp_r = (int*)sym_addr(g_rp_r);
    int*   rp_c = (int*)sym_addr(g_rp_c);
    int*   ce_v = (int*)sym_addr(g_ce_v);
    int*   ce_r = (int*)sym_addr(g_ce_r);
    int*   ce_c = (int*)sym_addr(g_ce_c);
    float* b0   = (float*)sym_addr(g_b0);
    float* b1   = (float*)sym_addr(g_b1);
    float* b2   = (float*)sym_addr(g_b2);
    float* bu0  = (float*)sym_addr(g_bu0);
    float* bu1  = (float*)sym_addr(g_bu1);
    float* p1   = (float*)sym_addr(g_p1);
    float* u1   = (float*)sym_addr(g_u1);

    float* out_p = (float*)d_out;                    // [NP,16]
    float* out_u = (float*)d_out + (size_t)NP * 16;  // [NU,16]

    const int TB = 256;
    const int eb = (E + TB - 1) / TB;

    // ---- fused CSR build for all 3 edge types ----
    cudaMemsetAsync(deg3, 0, (size_t)(NU + 2 * NP) * sizeof(int));
    count3_kernel<<<eb, TB>>>(ev_dst, er_dst, ec_dst, E, deg3);
    scan_bs3<<<NB_TOT, 1024>>>(deg3, part);
    scan_top3<<<3, 256>>>(part);
    scan_final3<<<NB_TOT, 1024>>>(deg3, part, rp_v, rp_r, rp_c, cur3);
    scatter3_kernel<<<eb, TB>>>(ev_src, ev_dst, er_src, er_dst, ec_src, ec_dst,
                                E, cur3, ce_v, ce_r, ce_c);

    auto gblk = [&](int n) { return (n + 7) / 8; };   // warp per node, 256 thr/block

    // ================= layer 1 =================
    // P-input transforms: b0 = xp@W1v_l ; b1 = xp@W1c_l ; b2 = xp@(W1r_r+W1c_r)+b1r+b1c
    {
        TSlots t = {};
        t.Wa[0] = W1v_l;                       t.out[0] = b0;
        t.Wa[1] = W1c_l;                       t.out[1] = b1;
        t.Wa[2] = W1r_r; t.Wb[2] = W1c_r;
        t.ba[2] = b1r;   t.bb[2] = b1c;        t.out[2] = b2;
        transform_fused<64, 3><<<(NP + TB - 1) / TB, TB>>>(xp, NP, t);
    }
    // U-input transforms: bu0 = xu@W1r_l ; bu1 = xu@W1v_r + b1v
    {
        TSlots t = {};
        t.Wa[0] = W1r_l;                       t.out[0] = bu0;
        t.Wa[1] = W1v_r; t.ba[1] = b1v;        t.out[1] = bu1;
        transform_fused<32, 2><<<(NU + TB - 1) / TB, TB>>>(xu, NU, t);
    }
    gather1_kernel<<<gblk(NU), TB>>>(rp_v, ce_v, (const float4*)b0,
                                     (const float4*)bu1, (float4*)u1, NU);
    gather2_kernel<<<gblk(NP), TB>>>(rp_r, ce_r, (const float4*)bu0,
                                     rp_c, ce_c, (const float4*)b1,
                                     (const float4*)b2, (float4*)p1, NP);

    // ================= layer 2 =================
    // P-input transforms: b0 = p1@W2v_l ; b1 = p1@W2c_l ; b2 = p1@(W2r_r+W2c_r)+b2r+b2c
    {
        TSlots t = {};
        t.Wa[0] = W2v_l;                       t.out[0] = b0;
        t.Wa[1] = W2c_l;                       t.out[1] = b1;
        t.Wa[2] = W2r_r; t.Wb[2] = W2c_r;
        t.ba[2] = b2r;   t.bb[2] = b2c;        t.out[2] = b2;
        transform_fused<16, 3><<<(NP + TB - 1) / TB, TB>>>(p1, NP, t);
    }
    // U-input transforms: bu0 = u1@W2r_l ; bu1 = u1@W2v_r + b2v
    {
        TSlots t = {};
        t.Wa[0] = W2r_l;                       t.out[0] = bu0;
        t.Wa[1] = W2v_r; t.ba[1] = b2v;        t.out[1] = bu1;
        transform_fused<16, 2><<<(NU + TB - 1) / TB, TB>>>(u1, NU, t);
    }
    gather1_kernel<<<gblk(NU), TB>>>(rp_v, ce_v, (const float4*)b0,
                                     (const float4*)bu1, (float4*)out_u, NU);
    gather2_kernel<<<gblk(NP), TB>>>(rp_r, ce_r, (const float4*)bu0,
                                     rp_c, ce_c, (const float4*)b1,
                                     (const float4*)b2, (float4*)out_p, NP);
}

// round 4
// speedup vs baseline: 1.1726x; 1.0153x over previous
#include <cuda_runtime.h>
#include <cuda_fp16.h>
#include <cstddef>

#define NP_C 200000
#define NU_C 50000
#define E_C  2000000

#define NB_U ((NU_C + 1023) / 1024)            // 49
#define NB_P ((NP_C + 1023) / 1024)            // 196
#define NB_TOT (NB_U + NB_P + NB_P)            // 441

// ---------------- device scratch (BSS, no allocation) ----------------
// combined degree/cursor/invdeg arrays: [0,NU)=v, [NU,NU+NP)=r, [NU+NP,NU+2NP)=c
__device__ int    g_deg3[NU_C + 2 * NP_C];
__device__ int    g_cur3[NU_C + 2 * NP_C];
__device__ float  g_inv3[NU_C + 2 * NP_C];
__device__ int    g_part[3 * 256];
__device__ int    g_rp_v[NU_C + 1];
__device__ int    g_rp_r[NP_C + 1];
__device__ int    g_rp_c[NP_C + 1];
__device__ int    g_ce_v[E_C];
__device__ int    g_ce_r[E_C];
__device__ int    g_ce_c[E_C];
// fp16 gather-source buffers (16 halves = 32B = 2 int4 per node); a = layer1, b = layer2
__device__ int4   g_h0a[NP_C * 2],  g_h0b[NP_C * 2];   // P src for gather1 (visita)
__device__ int4   g_h1a[NP_C * 2],  g_h1b[NP_C * 2];   // P src for gather2 segB (conoce)
__device__ int4   g_hu0a[NU_C * 2], g_hu0b[NU_C * 2];  // U src for gather2 segA (rev)
// fp32 self-term buffers
__device__ float4 g_b2a[NP_C * 4],  g_b2b[NP_C * 4];
__device__ float4 g_bu1a[NU_C * 4], g_bu1b[NU_C * 4];
// layer-1 activations (fp32)
__device__ float4 g_p1[NP_C * 4];
__device__ float4 g_u1[NU_C * 4];

// ---------------- fused CSR build ----------------
__global__ void __launch_bounds__(256)
count3_kernel(const int* __restrict__ dv, const int* __restrict__ dr,
              const int* __restrict__ dc, int e, int* __restrict__ deg3) {
    int i = blockIdx.x * blockDim.x + threadIdx.x;
    if (i >= e) return;
    int a = __ldg(&dv[i]);
    int b = __ldg(&dr[i]);
    int c = __ldg(&dc[i]);
    atomicAdd(&deg3[a], 1);
    atomicAdd(&deg3[NU_C + b], 1);
    atomicAdd(&deg3[NU_C + NP_C + c], 1);
}

__device__ __forceinline__ void seg_decode(int blk, int& seg, int& lb, int& base, int& n) {
    if (blk < NB_U)            { seg = 0; lb = blk;               base = 0;            n = NU_C; }
    else if (blk < NB_U + NB_P){ seg = 1; lb = blk - NB_U;        base = NU_C;         n = NP_C; }
    else                       { seg = 2; lb = blk - NB_U - NB_P; base = NU_C + NP_C;  n = NP_C; }
}

__global__ void scan_bs3(const int* __restrict__ deg3, int* __restrict__ part) {
    __shared__ int s[1024];
    int seg, lb, base, n;
    seg_decode(blockIdx.x, seg, lb, base, n);
    int tid = threadIdx.x;
    int i = lb * 1024 + tid;
    s[tid] = (i < n) ? deg3[base + i] : 0;
    __syncthreads();
    #pragma unroll
    for (int o = 512; o > 0; o >>= 1) {
        if (tid < o) s[tid] += s[tid + o];
        __syncthreads();
    }
    if (tid == 0) part[seg * 256 + lb] = s[0];
}

__global__ void scan_top3(int* __restrict__ part) {
    __shared__ int s[256];
    int seg = blockIdx.x;
    int nb = (seg == 0) ? NB_U : NB_P;
    int tid = threadIdx.x;
    int v = (tid < nb) ? part[seg * 256 + tid] : 0;
    s[tid] = v;
    __syncthreads();
    #pragma unroll
    for (int o = 1; o < 256; o <<= 1) {
        int t = (tid >= o) ? s[tid - o] : 0;
        __syncthreads();
        s[tid] += t;
        __syncthreads();
    }
    if (tid < nb) part[seg * 256 + tid] = s[tid] - v;   // exclusive
}

__global__ void scan_final3(const int* __restrict__ deg3, const int* __restrict__ part,
                            int* __restrict__ rp_v, int* __restrict__ rp_r,
                            int* __restrict__ rp_c, int* __restrict__ cur3,
                            float* __restrict__ inv3) {
    __shared__ int s[1024];
    int seg, lb, base, n;
    seg_decode(blockIdx.x, seg, lb, base, n);
    int* rp = (seg == 0) ? rp_v : (seg == 1) ? rp_r : rp_c;
    int tid = threadIdx.x;
    int i = lb * 1024 + tid;
    int v = (i < n) ? deg3[base + i] : 0;
    s[tid] = v;
    __syncthreads();
    #pragma unroll
    for (int o = 1; o < 1024; o <<= 1) {
        int t = (tid >= o) ? s[tid - o] : 0;
        __syncthreads();
        s[tid] += t;
        __syncthreads();
    }
    if (i < n) {
        int incl = part[seg * 256 + lb] + s[tid];
        rp[i + 1] = incl;
        cur3[base + i] = incl - v;
        inv3[base + i] = (v > 0) ? (1.0f / (float)v) : 0.f;
        if (i == 0) rp[0] = 0;
    }
}

__global__ void __launch_bounds__(256)
scatter3_kernel(const int* __restrict__ sv, const int* __restrict__ dv,
                const int* __restrict__ sr, const int* __restrict__ dr,
                const int* __restrict__ sc, const int* __restrict__ dc,
                int e, int* __restrict__ cur3,
                int* __restrict__ ce_v, int* __restrict__ ce_r, int* __restrict__ ce_c) {
    int i = blockIdx.x * blockDim.x + threadIdx.x;
    if (i >= e) return;
    int s0 = __ldg(&sv[i]); int d0 = __ldg(&dv[i]);
    int s1 = __ldg(&sr[i]); int d1 = __ldg(&dr[i]);
    int s2 = __ldg(&sc[i]); int d2 = __ldg(&dc[i]);
    int p0 = atomicAdd(&cur3[d0], 1);
    int p1 = atomicAdd(&cur3[NU_C + d1], 1);
    int p2 = atomicAdd(&cur3[NU_C + NP_C + d2], 1);
    ce_v[p0] = s0;
    ce_r[p1] = s1;
    ce_c[p2] = s2;
}

// ---------------- fused node transforms ----------------
// out[s][n,16] = x[n,F] @ (Wa[s] [+Wb[s]]) [+ ba[s]+bb[s]]
// HMASK bit s set -> out[s] stored as fp16 (gather source); else fp32 (self term).
// 2 rows per thread to halve shared-weight LDS per FMA.
struct TSlots {
    const float* Wa[3];
    const float* Wb[3];
    const float* ba[3];
    const float* bb[3];
    void*        out[3];
};

template <int F, int NS, int HMASK>
__global__ void __launch_bounds__(256)
transform_fused(const float* __restrict__ x, int n, TSlots t) {
    constexpr int R = 2;
    __shared__ float Ws[NS * F * 16];
    __shared__ float bs[NS * 16];
    int tid = threadIdx.x;
    for (int i = tid; i < NS * F * 16; i += 256) {
        int s = i / (F * 16);
        int j = i % (F * 16);
        float w = t.Wa[s][j];
        if (t.Wb[s]) w += t.Wb[s][j];
        Ws[i] = w;
    }
    if (tid < NS * 16) {
        int s = tid >> 4, c = tid & 15;
        float b = 0.f;
        if (t.ba[s]) b += t.ba[s][c];
        if (t.bb[s]) b += t.bb[s][c];
        bs[tid] = b;
    }
    __syncthreads();
    int base = blockIdx.x * (256 * R) + tid;
    int rows[R];
    float acc[R][NS * 16];
    #pragma unroll
    for (int rr = 0; rr < R; rr++) {
        rows[rr] = base + rr * 256;
        #pragma unroll
        for (int i = 0; i < NS * 16; i++) acc[rr][i] = bs[i];
    }
    #pragma unroll
    for (int k4 = 0; k4 < F / 4; k4++) {
        float4 v[R];
        #pragma unroll
        for (int rr = 0; rr < R; rr++)
            if (rows[rr] < n)
                v[rr] = __ldg(reinterpret_cast<const float4*>(x + (size_t)rows[rr] * F) + k4);
        #pragma unroll
        for (int s = 0; s < NS; s++) {
            const float* w0 = &Ws[(s * F + 4 * k4) * 16];
            #pragma unroll
            for (int c = 0; c < 16; c++) {
                float wa = w0[c], wb = w0[16 + c], wc = w0[32 + c], wd = w0[48 + c];
                #pragma unroll
                for (int rr = 0; rr < R; rr++) {
                    float a = acc[rr][s * 16 + c];
                    a = fmaf(v[rr].x, wa, a);
                    a = fmaf(v[rr].y, wb, a);
                    a = fmaf(v[rr].z, wc, a);
                    a = fmaf(v[rr].w, wd, a);
                    acc[rr][s * 16 + c] = a;
                }
            }
        }
    }
    #pragma unroll
    for (int rr = 0; rr < R; rr++) {
        if (rows[rr] >= n) continue;
        #pragma unroll
        for (int s = 0; s < NS; s++) {
            if (HMASK & (1 << s)) {
                __half2 h[8];
                #pragma unroll
                for (int q = 0; q < 8; q++)
                    h[q] = __floats2half2_rn(acc[rr][s * 16 + 2 * q],
                                             acc[rr][s * 16 + 2 * q + 1]);
                int4* o = (int4*)t.out[s] + (size_t)rows[rr] * 2;
                o[0] = *reinterpret_cast<int4*>(&h[0]);
                o[1] = *reinterpret_cast<int4*>(&h[4]);
            } else {
                float4* o = (float4*)t.out[s] + (size_t)rows[rr] * 4;
                #pragma unroll
                for (int q = 0; q < 4; q++)
                    o[q] = make_float4(acc[rr][s * 16 + 4 * q], acc[rr][s * 16 + 4 * q + 1],
                                       acc[rr][s * 16 + 4 * q + 2], acc[rr][s * 16 + 4 * q + 3]);
            }
        }
    }
}

// ---------------- gathers: warp/node, 2 lanes per fp16 row (16B each), 16 edge groups ----------------
__device__ __forceinline__ void acc8(float* a, int4 v) {
    float2 f0 = __half22float2(*reinterpret_cast<__half2*>(&v.x));
    float2 f1 = __half22float2(*reinterpret_cast<__half2*>(&v.y));
    float2 f2 = __half22float2(*reinterpret_cast<__half2*>(&v.z));
    float2 f3 = __half22float2(*reinterpret_cast<__half2*>(&v.w));
    a[0] += f0.x; a[1] += f0.y; a[2] += f1.x; a[3] += f1.y;
    a[4] += f2.x; a[5] += f2.y; a[6] += f3.x; a[7] += f3.y;
}

__device__ __forceinline__ void gather_seg(const int* __restrict__ ce,
                                           const int4* __restrict__ tsrc,
                                           int beg, int end, int g, int q, float* a) {
    int e = beg + g;
    for (; e + 16 < end; e += 32) {
        int s0 = __ldg(&ce[e]);
        int s1 = __ldg(&ce[e + 16]);
        int4 v0 = __ldg(&tsrc[s0 * 2 + q]);
        int4 v1 = __ldg(&tsrc[s1 * 2 + q]);
        acc8(a, v0);
        acc8(a, v1);
    }
    if (e < end) {
        int s0 = __ldg(&ce[e]);
        acc8(a, __ldg(&tsrc[s0 * 2 + q]));
    }
}

__device__ __forceinline__ void red_groups8(float* a) {
    #pragma unroll
    for (int m = 2; m <= 16; m <<= 1) {
        #pragma unroll
        for (int i = 0; i < 8; i++)
            a[i] += __shfl_xor_sync(0xffffffffu, a[i], m);
    }
}

__global__ void __launch_bounds__(256)
gather1_kernel(const int* __restrict__ rp, const int* __restrict__ ce,
               const float* __restrict__ invd,
               const int4* __restrict__ tsrc, const float4* __restrict__ tself,
               float4* __restrict__ out, int n) {
    int w = (blockIdx.x * 256 + threadIdx.x) >> 5;
    if (w >= n) return;
    int lane = threadIdx.x & 31;
    int g = lane >> 1, q = lane & 1;
    int beg = __ldg(&rp[w]), end = __ldg(&rp[w + 1]);
    float a[8] = {0.f, 0.f, 0.f, 0.f, 0.f, 0.f, 0.f, 0.f};
    gather_seg(ce, tsrc, beg, end, g, q, a);
    red_groups8(a);
    if (lane < 2) {
        float inv = __ldg(&invd[w]);
        float4 s0 = __ldg(&tself[w * 4 + q * 2]);
        float4 s1 = __ldg(&tself[w * 4 + q * 2 + 1]);
        float4 o0, o1;
        o0.x = fmaxf(fmaf(a[0], inv, s0.x), 0.f);
        o0.y = fmaxf(fmaf(a[1], inv, s0.y), 0.f);
        o0.z = fmaxf(fmaf(a[2], inv, s0.z), 0.f);
        o0.w = fmaxf(fmaf(a[3], inv, s0.w), 0.f);
        o1.x = fmaxf(fmaf(a[4], inv, s1.x), 0.f);
        o1.y = fmaxf(fmaf(a[5], inv, s1.y), 0.f);
        o1.z = fmaxf(fmaf(a[6], inv, s1.z), 0.f);
        o1.w = fmaxf(fmaf(a[7], inv, s1.w), 0.f);
        out[w * 4 + q * 2] = o0;
        out[w * 4 + q * 2 + 1] = o1;
    }
}

__global__ void __launch_bounds__(256)
gather2_kernel(const int* __restrict__ rpA, const int* __restrict__ ceA,
               const float* __restrict__ invA_d, const int4* __restrict__ tA,
               const int* __restrict__ rpB, const int* __restrict__ ceB,
               const float* __restrict__ invB_d, const int4* __restrict__ tB,
               const float4* __restrict__ tself, float4* __restrict__ out, int n) {
    int w = (blockIdx.x * 256 + threadIdx.x) >> 5;
    if (w >= n) return;
    int lane = threadIdx.x & 31;
    int g = lane >> 1, q = lane & 1;
    int begA = __ldg(&rpA[w]), endA = __ldg(&rpA[w + 1]);
    int begB = __ldg(&rpB[w]), endB = __ldg(&rpB[w + 1]);
    float aA[8] = {0.f, 0.f, 0.f, 0.f, 0.f, 0.f, 0.f, 0.f};
    float aB[8] = {0.f, 0.f, 0.f, 0.f, 0.f, 0.f, 0.f, 0.f};
    gather_seg(ceA, tA, begA, endA, g, q, aA);
    gather_seg(ceB, tB, begB, endB, g, q, aB);
    red_groups8(aA);
    red_groups8(aB);
    if (lane < 2) {
        float invA = __ldg(&invA_d[w]);
        float invB = __ldg(&invB_d[w]);
        float4 s0 = __ldg(&tself[w * 4 + q * 2]);
        float4 s1 = __ldg(&tself[w * 4 + q * 2 + 1]);
        float4 o0, o1;
        o0.x = fmaxf(fmaf(aA[0], invA, fmaf(aB[0], invB, s0.x)), 0.f);
        o0.y = fmaxf(fmaf(aA[1], invA, fmaf(aB[1], invB, s0.y)), 0.f);
        o0.z = fmaxf(fmaf(aA[2], invA, fmaf(aB[2], invB, s0.z)), 0.f);
        o0.w = fmaxf(fmaf(aA[3], invA, fmaf(aB[3], invB, s0.w)), 0.f);
        o1.x = fmaxf(fmaf(aA[4], invA, fmaf(aB[4], invB, s1.x)), 0.f);
        o1.y = fmaxf(fmaf(aA[5], invA, fmaf(aB[5], invB, s1.y)), 0.f);
        o1.z = fmaxf(fmaf(aA[6], invA, fmaf(aB[6], invB, s1.z)), 0.f);
        o1.w = fmaxf(fmaf(aA[7], invA, fmaf(aB[7], invB, s1.w)), 0.f);
        out[w * 4 + q * 2] = o0;
        out[w * 4 + q * 2 + 1] = o1;
    }
}

// ---------------- host launcher ----------------
static inline void* sym_addr(const void* symbol) {
    void* p = nullptr;
    cudaGetSymbolAddress(&p, symbol);
    return p;
}

extern "C" void kernel_launch(void* const* d_in, const int* in_sizes, int n_in,
                              void* d_out, int out_size) {
    const float* xp = (const float*)d_in[0];
    const float* xu = (const float*)d_in[1];
    const int* ev_src = (const int*)d_in[2];
    const int* ev_dst = (const int*)d_in[3];
    const int* er_src = (const int*)d_in[4];
    const int* er_dst = (const int*)d_in[5];
    const int* ec_src = (const int*)d_in[6];
    const int* ec_dst = (const int*)d_in[7];
    const float* W1v_l = (const float*)d_in[8];
    const float* W1v_r = (const float*)d_in[9];
    const float* b1v   = (const float*)d_in[10];
    const float* W1r_l = (const float*)d_in[11];
    const float* W1r_r = (const float*)d_in[12];
    const float* b1r   = (const float*)d_in[13];
    const float* W1c_l = (const float*)d_in[14];
    const float* W1c_r = (const float*)d_in[15];
    const float* b1c   = (const float*)d_in[16];
    const float* W2v_l = (const float*)d_in[17];
    const float* W2v_r = (const float*)d_in[18];
    const float* b2v   = (const float*)d_in[19];
    const float* W2r_l = (const float*)d_in[20];
    const float* W2r_r = (const float*)d_in[21];
    const float* b2r   = (const float*)d_in[22];
    const float* W2c_l = (const float*)d_in[23];
    const float* W2c_r = (const float*)d_in[24];
    const float* b2c   = (const float*)d_in[25];

    const int NP = NP_C, NU = NU_C, E = E_C;

    int*    deg3 = (int*)sym_addr(g_deg3);
    int*    cur3 = (int*)sym_addr(g_cur3);
    float*  inv3 = (float*)sym_addr(g_inv3);
    int*    part = (int*)sym_addr(g_part);
    int*    rp_v = (int*)sym_addr(g_rp_v);
    int*    rp_r = (int*)sym_addr(g_rp_r);
    int*    rp_c = (int*)sym_addr(g_rp_c);
    int*    ce_v = (int*)sym_addr(g_ce_v);
    int*    ce_r = (int*)sym_addr(g_ce_r);
    int*    ce_c = (int*)sym_addr(g_ce_c);
    int4*   h0a  = (int4*)sym_addr(g_h0a);
    int4*   h0b  = (int4*)sym_addr(g_h0b);
    int4*   h1a  = (int4*)sym_addr(g_h1a);
    int4*   h1b  = (int4*)sym_addr(g_h1b);
    int4*   hu0a = (int4*)sym_addr(g_hu0a);
    int4*   hu0b = (int4*)sym_addr(g_hu0b);
    float4* b2a  = (float4*)sym_addr(g_b2a);
    float4* b2b  = (float4*)sym_addr(g_b2b);
    float4* bu1a = (float4*)sym_addr(g_bu1a);
    float4* bu1b = (float4*)sym_addr(g_bu1b);
    float4* p1   = (float4*)sym_addr(g_p1);
    float4* u1   = (float4*)sym_addr(g_u1);

    float4* out_p = (float4*)d_out;                              // [NP,16]
    float4* out_u = (float4*)((float*)d_out + (size_t)NP * 16);  // [NU,16]

    const int TB = 256;
    const int eb = (E + TB - 1) / TB;
    const int gP = (NP + 511) / 512;   // transform: 2 rows/thread
    const int gU = (NU + 511) / 512;
    auto gblk = [&](int n) { return (n + 7) / 8; };   // gather: warp per node

    // one-time host infra (streams/events; no device memory)
    static cudaStream_t s2 = nullptr;
    static cudaEvent_t evF = nullptr, evCSR = nullptr, evT = nullptr, evB = nullptr;
    if (!s2) {
        cudaStreamCreateWithFlags(&s2, cudaStreamNonBlocking);
        cudaEventCreateWithFlags(&evF, cudaEventDisableTiming);
        cudaEventCreateWithFlags(&evCSR, cudaEventDisableTiming);
        cudaEventCreateWithFlags(&evT, cudaEventDisableTiming);
        cudaEventCreateWithFlags(&evB, cudaEventDisableTiming);
    }

    // ---- fork: CSR build (stream 0) || layer-1 transforms (s2) ----
    cudaEventRecord(evF, 0);
    cudaStreamWaitEvent(s2, evF, 0);

    cudaMemsetAsync(deg3, 0, (size_t)(NU + 2 * NP) * sizeof(int), 0);
    count3_kernel<<<eb, TB>>>(ev_dst, er_dst, ec_dst, E, deg3);
    scan_bs3<<<NB_TOT, 1024>>>(deg3, part);
    scan_top3<<<3, 256>>>(part);
    scan_final3<<<NB_TOT, 1024>>>(deg3, part, rp_v, rp_r, rp_c, cur3, inv3);
    scatter3_kernel<<<eb, TB>>>(ev_src, ev_dst, er_src, er_dst, ec_src, ec_dst,
                                E, cur3, ce_v, ce_r, ce_c);
    cudaEventRecord(evCSR, 0);

    {   // P transforms: h0a = xp@W1v_l (fp16); h1a = xp@W1c_l (fp16); b2a = xp@(W1r_r+W1c_r)+b1r+b1c
        TSlots t = {};
        t.Wa[0] = W1v_l;                     t.out[0] = h0a;
        t.Wa[1] = W1c_l;                     t.out[1] = h1a;
        t.Wa[2] = W1r_r; t.Wb[2] = W1c_r;
        t.ba[2] = b1r;   t.bb[2] = b1c;      t.out[2] = b2a;
        transform_fused<64, 3, 3><<<gP, TB, 0, s2>>>(xp, NP, t);
    }
    {   // U transforms: hu0a = xu@W1r_l (fp16); bu1a = xu@W1v_r + b1v
        TSlots t = {};
        t.Wa[0] = W1r_l;                     t.out[0] = hu0a;
        t.Wa[1] = W1v_r; t.ba[1] = b1v;      t.out[1] = bu1a;
        transform_fused<32, 2, 1><<<gU, TB, 0, s2>>>(xu, NU, t);
    }
    cudaEventRecord(evT, s2);

    // join both ways: each branch below needs CSR AND layer-1 transforms
    cudaStreamWaitEvent(s2, evCSR, 0);
    cudaStreamWaitEvent(0, evT, 0);

    // ---- branch s2 (U side): gather1 L1 -> u1; then L2 U transforms -> hu0b/bu1b ----
    gather1_kernel<<<gblk(NU), TB, 0, s2>>>(rp_v, ce_v, inv3, h0a, bu1a, u1, NU);
    {
        TSlots t = {};
        t.Wa[0] = W2r_l;                     t.out[0] = hu0b;
        t.Wa[1] = W2v_r; t.ba[1] = b2v;      t.out[1] = bu1b;
        transform_fused<16, 2, 1><<<gU, TB, 0, s2>>>((const float*)u1, NU, t);
    }
    cudaEventRecord(evB, s2);

    // ---- branch 0 (P side): gather2 L1 -> p1; then L2 P transforms -> h0b/h1b/b2b ----
    gather2_kernel<<<gblk(NP), TB>>>(rp_r, ce_r, inv3 + NU, hu0a,
                                     rp_c, ce_c, inv3 + NU + NP, h1a,
                                     b2a, p1, NP);
    {
        TSlots t = {};
        t.Wa[0] = W2v_l;                     t.out[0] = h0b;
        t.Wa[1] = W2c_l;                     t.out[1] = h1b;
        t.Wa[2] = W2r_r; t.Wb[2] = W2c_r;
        t.ba[2] = b2r;   t.bb[2] = b2c;      t.out[2] = b2b;
        transform_fused<16, 3, 3><<<gP, TB>>>((const float*)p1, NP, t);
    }

    // ---- join, final gathers ----
    cudaStreamWaitEvent(0, evB, 0);
    gather1_kernel<<<gblk(NU), TB>>>(rp_v, ce_v, inv3, h0b, bu1b, out_u, NU);
    gather2_kernel<<<gblk(NP), TB>>>(rp_r, ce_r, inv3 + NU, hu0b,
                                     rp_c, ce_c, inv3 + NU + NP, h1b,
                                     b2b, out_p, NP);
}

// round 5
// speedup vs baseline: 1.5919x; 1.3575x over previous
#include <cuda_runtime.h>
#include <cuda_fp16.h>
#include <cstddef>

#define NP_C 200000
#define NU_C 50000
#define E_C  2000000

#define NB_U ((NU_C + 1023) / 1024)            // 49
#define NB_P ((NP_C + 1023) / 1024)            // 196
#define NB_TOT (NB_U + NB_P + NB_P)            // 441

// ---------------- device scratch (BSS, no allocation) ----------------
// combined degree/cursor/invdeg arrays: [0,NU)=v, [NU,NU+NP)=r, [NU+NP,NU+2NP)=c
__device__ int    g_deg3[NU_C + 2 * NP_C];
__device__ int    g_cur3[NU_C + 2 * NP_C];
__device__ float  g_inv3[NU_C + 2 * NP_C];
__device__ int    g_part[3 * 256];
__device__ int    g_rp_v[NU_C + 1];
__device__ int    g_rp_r[NP_C + 1];
__device__ int    g_rp_c[NP_C + 1];
__device__ int    g_ce_v[E_C];
__device__ int    g_ce_r[E_C];
__device__ int    g_ce_c[E_C];
// fp16 gather-source buffers (16 halves = 32B = 2 int4 per node); a = layer1, b = layer2
__device__ int4   g_h0a[NP_C * 2],  g_h0b[NP_C * 2];   // P src for visita gather
__device__ int4   g_h1a[NP_C * 2],  g_h1b[NP_C * 2];   // P src for conoce gather
__device__ int4   g_hu0a[NU_C * 2], g_hu0b[NU_C * 2];  // U src for rev gather
// fp32 self-term buffers
__device__ float4 g_b2a[NP_C * 4],  g_b2b[NP_C * 4];
__device__ float4 g_bu1a[NU_C * 4], g_bu1b[NU_C * 4];
// layer-1 activations (fp32)
__device__ float4 g_p1[NP_C * 4];
__device__ float4 g_u1[NU_C * 4];

// ---------------- fused CSR build ----------------
__global__ void __launch_bounds__(256)
count3_kernel(const int* __restrict__ dv, const int* __restrict__ dr,
              const int* __restrict__ dc, int e, int* __restrict__ deg3) {
    int i = blockIdx.x * blockDim.x + threadIdx.x;
    if (i >= e) return;
    int a = __ldg(&dv[i]);
    int b = __ldg(&dr[i]);
    int c = __ldg(&dc[i]);
    atomicAdd(&deg3[a], 1);
    atomicAdd(&deg3[NU_C + b], 1);
    atomicAdd(&deg3[NU_C + NP_C + c], 1);
}

__device__ __forceinline__ void seg_decode(int blk, int& seg, int& lb, int& base, int& n) {
    if (blk < NB_U)            { seg = 0; lb = blk;               base = 0;            n = NU_C; }
    else if (blk < NB_U + NB_P){ seg = 1; lb = blk - NB_U;        base = NU_C;         n = NP_C; }
    else                       { seg = 2; lb = blk - NB_U - NB_P; base = NU_C + NP_C;  n = NP_C; }
}

__global__ void scan_bs3(const int* __restrict__ deg3, int* __restrict__ part) {
    __shared__ int s[1024];
    int seg, lb, base, n;
    seg_decode(blockIdx.x, seg, lb, base, n);
    int tid = threadIdx.x;
    int i = lb * 1024 + tid;
    s[tid] = (i < n) ? deg3[base + i] : 0;
    __syncthreads();
    #pragma unroll
    for (int o = 512; o > 0; o >>= 1) {
        if (tid < o) s[tid] += s[tid + o];
        __syncthreads();
    }
    if (tid == 0) part[seg * 256 + lb] = s[0];
}

__global__ void scan_top3(int* __restrict__ part) {
    __shared__ int s[256];
    int seg = blockIdx.x;
    int nb = (seg == 0) ? NB_U : NB_P;
    int tid = threadIdx.x;
    int v = (tid < nb) ? part[seg * 256 + tid] : 0;
    s[tid] = v;
    __syncthreads();
    #pragma unroll
    for (int o = 1; o < 256; o <<= 1) {
        int t = (tid >= o) ? s[tid - o] : 0;
        __syncthreads();
        s[tid] += t;
        __syncthreads();
    }
    if (tid < nb) part[seg * 256 + tid] = s[tid] - v;   // exclusive
}

__global__ void scan_final3(const int* __restrict__ deg3, const int* __restrict__ part,
                            int* __restrict__ rp_v, int* __restrict__ rp_r,
                            int* __restrict__ rp_c, int* __restrict__ cur3,
                            float* __restrict__ inv3) {
    __shared__ int s[1024];
    int seg, lb, base, n;
    seg_decode(blockIdx.x, seg, lb, base, n);
    int* rp = (seg == 0) ? rp_v : (seg == 1) ? rp_r : rp_c;
    int tid = threadIdx.x;
    int i = lb * 1024 + tid;
    int v = (i < n) ? deg3[base + i] : 0;
    s[tid] = v;
    __syncthreads();
    #pragma unroll
    for (int o = 1; o < 1024; o <<= 1) {
        int t = (tid >= o) ? s[tid - o] : 0;
        __syncthreads();
        s[tid] += t;
        __syncthreads();
    }
    if (i < n) {
        int incl = part[seg * 256 + lb] + s[tid];
        rp[i + 1] = incl;
        cur3[base + i] = incl - v;
        inv3[base + i] = (v > 0) ? (1.0f / (float)v) : 0.f;
        if (i == 0) rp[0] = 0;
    }
}

__global__ void __launch_bounds__(256)
scatter3_kernel(const int* __restrict__ sv, const int* __restrict__ dv,
                const int* __restrict__ sr, const int* __restrict__ dr,
                const int* __restrict__ sc, const int* __restrict__ dc,
                int e, int* __restrict__ cur3,
                int* __restrict__ ce_v, int* __restrict__ ce_r, int* __restrict__ ce_c) {
    int i = blockIdx.x * blockDim.x + threadIdx.x;
    if (i >= e) return;
    int s0 = __ldg(&sv[i]); int d0 = __ldg(&dv[i]);
    int s1 = __ldg(&sr[i]); int d1 = __ldg(&dr[i]);
    int s2 = __ldg(&sc[i]); int d2 = __ldg(&dc[i]);
    int p0 = atomicAdd(&cur3[d0], 1);
    int p1 = atomicAdd(&cur3[NU_C + d1], 1);
    int p2 = atomicAdd(&cur3[NU_C + NP_C + d2], 1);
    ce_v[p0] = s0;
    ce_r[p1] = s1;
    ce_c[p2] = s2;
}

// ---------------- fused node transforms ----------------
// out[s][n,16] = x[n,F] @ (Wa[s] [+Wb[s]]) [+ ba[s]+bb[s]]
// HMASK bit s set -> out[s] stored as fp16 (gather source); else fp32 (self term).
struct TSlots {
    const float* Wa[3];
    const float* Wb[3];
    const float* ba[3];
    const float* bb[3];
    void*        out[3];
};

template <int F, int NS, int HMASK>
__global__ void __launch_bounds__(256)
transform_fused(const float* __restrict__ x, int n, TSlots t) {
    constexpr int R = 2;
    __shared__ float Ws[NS * F * 16];
    __shared__ float bs[NS * 16];
    int tid = threadIdx.x;
    for (int i = tid; i < NS * F * 16; i += 256) {
        int s = i / (F * 16);
        int j = i % (F * 16);
        float w = t.Wa[s][j];
        if (t.Wb[s]) w += t.Wb[s][j];
        Ws[i] = w;
    }
    if (tid < NS * 16) {
        int s = tid >> 4, c = tid & 15;
        float b = 0.f;
        if (t.ba[s]) b += t.ba[s][c];
        if (t.bb[s]) b += t.bb[s][c];
        bs[tid] = b;
    }
    __syncthreads();
    int base = blockIdx.x * (256 * R) + tid;
    int rows[R];
    float acc[R][NS * 16];
    #pragma unroll
    for (int rr = 0; rr < R; rr++) {
        rows[rr] = base + rr * 256;
        #pragma unroll
        for (int i = 0; i < NS * 16; i++) acc[rr][i] = bs[i];
    }
    #pragma unroll
    for (int k4 = 0; k4 < F / 4; k4++) {
        float4 v[R];
        #pragma unroll
        for (int rr = 0; rr < R; rr++)
            if (rows[rr] < n)
                v[rr] = __ldg(reinterpret_cast<const float4*>(x + (size_t)rows[rr] * F) + k4);
        #pragma unroll
        for (int s = 0; s < NS; s++) {
            const float* w0 = &Ws[(s * F + 4 * k4) * 16];
            #pragma unroll
            for (int c = 0; c < 16; c++) {
                float wa = w0[c], wb = w0[16 + c], wc = w0[32 + c], wd = w0[48 + c];
                #pragma unroll
                for (int rr = 0; rr < R; rr++) {
                    float a = acc[rr][s * 16 + c];
                    a = fmaf(v[rr].x, wa, a);
                    a = fmaf(v[rr].y, wb, a);
                    a = fmaf(v[rr].z, wc, a);
                    a = fmaf(v[rr].w, wd, a);
                    acc[rr][s * 16 + c] = a;
                }
            }
        }
    }
    #pragma unroll
    for (int rr = 0; rr < R; rr++) {
        if (rows[rr] >= n) continue;
        #pragma unroll
        for (int s = 0; s < NS; s++) {
            if (HMASK & (1 << s)) {
                __half2 h[8];
                #pragma unroll
                for (int q = 0; q < 8; q++)
                    h[q] = __floats2half2_rn(acc[rr][s * 16 + 2 * q],
                                             acc[rr][s * 16 + 2 * q + 1]);
                int4* o = (int4*)t.out[s] + (size_t)rows[rr] * 2;
                o[0] = *reinterpret_cast<int4*>(&h[0]);
                o[1] = *reinterpret_cast<int4*>(&h[4]);
            } else {
                float4* o = (float4*)t.out[s] + (size_t)rows[rr] * 4;
                #pragma unroll
                for (int q = 0; q < 4; q++)
                    o[q] = make_float4(acc[rr][s * 16 + 4 * q], acc[rr][s * 16 + 4 * q + 1],
                                       acc[rr][s * 16 + 4 * q + 2], acc[rr][s * 16 + 4 * q + 3]);
            }
        }
    }
}

// ---------------- fused gather: 2 lanes per node, zero shuffles ----------------
// Lane q (0/1) of a node owns one 16B half (8 halves) of the 32B fp16 source row
// and the corresponding 8 fp32 dims of self/out. Edges are walked serially per
// lane (unrolled x2); no cross-lane reduction needed.
__device__ __forceinline__ void acc8(float* a, int4 v) {
    float2 f0 = __half22float2(*reinterpret_cast<__half2*>(&v.x));
    float2 f1 = __half22float2(*reinterpret_cast<__half2*>(&v.y));
    float2 f2 = __half22float2(*reinterpret_cast<__half2*>(&v.z));
    float2 f3 = __half22float2(*reinterpret_cast<__half2*>(&v.w));
    a[0] += f0.x; a[1] += f0.y; a[2] += f1.x; a[3] += f1.y;
    a[4] += f2.x; a[5] += f2.y; a[6] += f3.x; a[7] += f3.y;
}

__device__ __forceinline__ void lane_gather(const int* __restrict__ rp,
                                            const int* __restrict__ ce,
                                            const int4* __restrict__ tsrc,
                                            int node, int q, float* a) {
    int beg = __ldg(&rp[node]), end = __ldg(&rp[node + 1]);
    int e = beg;
    for (; e + 1 < end; e += 2) {
        int s0 = __ldg(&ce[e]);
        int s1 = __ldg(&ce[e + 1]);
        int4 v0 = __ldg(&tsrc[s0 * 2 + q]);
        int4 v1 = __ldg(&tsrc[s1 * 2 + q]);
        acc8(a, v0);
        acc8(a, v1);
    }
    if (e < end) {
        int s0 = __ldg(&ce[e]);
        acc8(a, __ldg(&tsrc[s0 * 2 + q]));
    }
}

__device__ __forceinline__ void store_node(float4* __restrict__ out, int node, int q,
                                           const float4* __restrict__ tself,
                                           const float* a, float inv,
                                           const float* b, float invB) {
    float4 s0 = __ldg(&tself[node * 4 + q * 2]);
    float4 s1 = __ldg(&tself[node * 4 + q * 2 + 1]);
    float4 o0, o1;
    o0.x = fmaf(a[0], inv, s0.x); o0.y = fmaf(a[1], inv, s0.y);
    o0.z = fmaf(a[2], inv, s0.z); o0.w = fmaf(a[3], inv, s0.w);
    o1.x = fmaf(a[4], inv, s1.x); o1.y = fmaf(a[5], inv, s1.y);
    o1.z = fmaf(a[6], inv, s1.z); o1.w = fmaf(a[7], inv, s1.w);
    if (b) {
        o0.x = fmaf(b[0], invB, o0.x); o0.y = fmaf(b[1], invB, o0.y);
        o0.z = fmaf(b[2], invB, o0.z); o0.w = fmaf(b[3], invB, o0.w);
        o1.x = fmaf(b[4], invB, o1.x); o1.y = fmaf(b[5], invB, o1.y);
        o1.z = fmaf(b[6], invB, o1.z); o1.w = fmaf(b[7], invB, o1.w);
    }
    o0.x = fmaxf(o0.x, 0.f); o0.y = fmaxf(o0.y, 0.f);
    o0.z = fmaxf(o0.z, 0.f); o0.w = fmaxf(o0.w, 0.f);
    o1.x = fmaxf(o1.x, 0.f); o1.y = fmaxf(o1.y, 0.f);
    o1.z = fmaxf(o1.z, 0.f); o1.w = fmaxf(o1.w, 0.f);
    out[node * 4 + q * 2] = o0;
    out[node * 4 + q * 2 + 1] = o1;
}

// One kernel does both node types for a layer: nodes [0,NU) = U (visita gather),
// nodes [NU, NU+NP) = P (rev + conoce gathers).
__global__ void __launch_bounds__(256)
gather_layer(const int* __restrict__ rp_v, const int* __restrict__ ce_v,
             const int4* __restrict__ srcV, const float4* __restrict__ selfU,
             float4* __restrict__ outU,
             const int* __restrict__ rp_r, const int* __restrict__ ce_r,
             const int4* __restrict__ srcR,
             const int* __restrict__ rp_c, const int* __restrict__ ce_c,
             const int4* __restrict__ srcC, const float4* __restrict__ selfP,
             float4* __restrict__ outP,
             const float* __restrict__ inv3, int nu, int np) {
    int gt = blockIdx.x * 256 + threadIdx.x;
    int node = gt >> 1;
    int q = gt & 1;
    if (node < nu) {
        float a[8] = {0.f, 0.f, 0.f, 0.f, 0.f, 0.f, 0.f, 0.f};
        lane_gather(rp_v, ce_v, srcV, node, q, a);
        store_node(outU, node, q, selfU, a, __ldg(&inv3[node]), nullptr, 0.f);
    } else if (node < nu + np) {
        int p = node - nu;
        float aR[8] = {0.f, 0.f, 0.f, 0.f, 0.f, 0.f, 0.f, 0.f};
        float aC[8] = {0.f, 0.f, 0.f, 0.f, 0.f, 0.f, 0.f, 0.f};
        lane_gather(rp_r, ce_r, srcR, p, q, aR);
        lane_gather(rp_c, ce_c, srcC, p, q, aC);
        store_node(outP, p, q, selfP, aR, __ldg(&inv3[nu + p]),
                   aC, __ldg(&inv3[nu + np + p]));
    }
}

// ---------------- host launcher ----------------
static inline void* sym_addr(const void* symbol) {
    void* p = nullptr;
    cudaGetSymbolAddress(&p, symbol);
    return p;
}

extern "C" void kernel_launch(void* const* d_in, const int* in_sizes, int n_in,
                              void* d_out, int out_size) {
    const float* xp = (const float*)d_in[0];
    const float* xu = (const float*)d_in[1];
    const int* ev_src = (const int*)d_in[2];
    const int* ev_dst = (const int*)d_in[3];
    const int* er_src = (const int*)d_in[4];
    const int* er_dst = (const int*)d_in[5];
    const int* ec_src = (const int*)d_in[6];
    const int* ec_dst = (const int*)d_in[7];
    const float* W1v_l = (const float*)d_in[8];
    const float* W1v_r = (const float*)d_in[9];
    const float* b1v   = (const float*)d_in[10];
    const float* W1r_l = (const float*)d_in[11];
    const float* W1r_r = (const float*)d_in[12];
    const float* b1r   = (const float*)d_in[13];
    const float* W1c_l = (const float*)d_in[14];
    const float* W1c_r = (const float*)d_in[15];
    const float* b1c   = (const float*)d_in[16];
    const float* W2v_l = (const float*)d_in[17];
    const float* W2v_r = (const float*)d_in[18];
    const float* b2v   = (const float*)d_in[19];
    const float* W2r_l = (const float*)d_in[20];
    const float* W2r_r = (const float*)d_in[21];
    const float* b2r   = (const float*)d_in[22];
    const float* W2c_l = (const float*)d_in[23];
    const float* W2c_r = (const float*)d_in[24];
    const float* b2c   = (const float*)d_in[25];

    const int NP = NP_C, NU = NU_C, E = E_C;

    int*    deg3 = (int*)sym_addr(g_deg3);
    int*    cur3 = (int*)sym_addr(g_cur3);
    float*  inv3 = (float*)sym_addr(g_inv3);
    int*    part = (int*)sym_addr(g_part);
    int*    rp_v = (int*)sym_addr(g_rp_v);
    int*    rp_r = (int*)sym_addr(g_rp_r);
    int*    rp_c = (int*)sym_addr(g_rp_c);
    int*    ce_v = (int*)sym_addr(g_ce_v);
    int*    ce_r = (int*)sym_addr(g_ce_r);
    int*    ce_c = (int*)sym_addr(g_ce_c);
    int4*   h0a  = (int4*)sym_addr(g_h0a);
    int4*   h0b  = (int4*)sym_addr(g_h0b);
    int4*   h1a  = (int4*)sym_addr(g_h1a);
    int4*   h1b  = (int4*)sym_addr(g_h1b);
    int4*   hu0a = (int4*)sym_addr(g_hu0a);
    int4*   hu0b = (int4*)sym_addr(g_hu0b);
    float4* b2a  = (float4*)sym_addr(g_b2a);
    float4* b2b  = (float4*)sym_addr(g_b2b);
    float4* bu1a = (float4*)sym_addr(g_bu1a);
    float4* bu1b = (float4*)sym_addr(g_bu1b);
    float4* p1   = (float4*)sym_addr(g_p1);
    float4* u1   = (float4*)sym_addr(g_u1);

    float4* out_p = (float4*)d_out;                              // [NP,16]
    float4* out_u = (float4*)((float*)d_out + (size_t)NP * 16);  // [NU,16]

    const int TB = 256;
    const int eb = (E + TB - 1) / TB;
    const int gP = (NP + 511) / 512;   // transform: 2 rows/thread
    const int gU = (NU + 511) / 512;
    const int gG = ((NU + NP) * 2 + TB - 1) / TB;   // fused gather grid

    // ---- CSR build for all 3 edge types ----
    cudaMemsetAsync(deg3, 0, (size_t)(NU + 2 * NP) * sizeof(int));
    count3_kernel<<<eb, TB>>>(ev_dst, er_dst, ec_dst, E, deg3);
    scan_bs3<<<NB_TOT, 1024>>>(deg3, part);
    scan_top3<<<3, 256>>>(part);
    scan_final3<<<NB_TOT, 1024>>>(deg3, part, rp_v, rp_r, rp_c, cur3, inv3);
    scatter3_kernel<<<eb, TB>>>(ev_src, ev_dst, er_src, er_dst, ec_src, ec_dst,
                                E, cur3, ce_v, ce_r, ce_c);

    // ================= layer 1 =================
    {   // P transforms: h0a = xp@W1v_l (fp16); h1a = xp@W1c_l (fp16); b2a = xp@(W1r_r+W1c_r)+b1r+b1c
        TSlots t = {};
        t.Wa[0] = W1v_l;                     t.out[0] = h0a;
        t.Wa[1] = W1c_l;                     t.out[1] = h1a;
        t.Wa[2] = W1r_r; t.Wb[2] = W1c_r;
        t.ba[2] = b1r;   t.bb[2] = b1c;      t.out[2] = b2a;
        transform_fused<64, 3, 3><<<gP, TB>>>(xp, NP, t);
    }
    {   // U transforms: hu0a = xu@W1r_l (fp16); bu1a = xu@W1v_r + b1v
        TSlots t = {};
        t.Wa[0] = W1r_l;                     t.out[0] = hu0a;
        t.Wa[1] = W1v_r; t.ba[1] = b1v;      t.out[1] = bu1a;
        transform_fused<32, 2, 1><<<gU, TB>>>(xu, NU, t);
    }
    gather_layer<<<gG, TB>>>(rp_v, ce_v, h0a, bu1a, u1,
                             rp_r, ce_r, hu0a, rp_c, ce_c, h1a, b2a, p1,
                             inv3, NU, NP);

    // ================= layer 2 =================
    {   // P transforms: h0b = p1@W2v_l ; h1b = p1@W2c_l ; b2b = p1@(W2r_r+W2c_r)+b2r+b2c
        TSlots t = {};
        t.Wa[0] = W2v_l;                     t.out[0] = h0b;
        t.Wa[1] = W2c_l;                     t.out[1] = h1b;
        t.Wa[2] = W2r_r; t.Wb[2] = W2c_r;
        t.ba[2] = b2r;   t.bb[2] = b2c;      t.out[2] = b2b;
        transform_fused<16, 3, 3><<<gP, TB>>>((const float*)p1, NP, t);
    }
    {   // U transforms: hu0b = u1@W2r_l ; bu1b = u1@W2v_r + b2v
        TSlots t = {};
        t.Wa[0] = W2r_l;                     t.out[0] = hu0b;
        t.Wa[1] = W2v_r; t.ba[1] = b2v;      t.out[1] = bu1b;
        transform_fused<16, 2, 1><<<gU, TB>>>((const float*)u1, NU, t);
    }
    gather_layer<<<gG, TB>>>(rp_v, ce_v, h0b, bu1b, out_u,
                             rp_r, ce_r, hu0b, rp_c, ce_c, h1b, b2b, out_p,
                             inv3, NU, NP);
}

// round 6
// speedup vs baseline: 1.6550x; 1.0396x over previous
#include <cuda_runtime.h>
#include <cuda_fp16.h>
#include <cstddef>

#define NP_C 200000
#define NU_C 50000
#define E_C  2000000

#define NB_U ((NU_C + 1023) / 1024)            // 49
#define NB_P ((NP_C + 1023) / 1024)            // 196
#define NB_TOT (NB_U + NB_P + NB_P)            // 441

// ---------------- device scratch (BSS, no allocation) ----------------
// combined degree/cursor/invdeg arrays: [0,NU)=v, [NU,NU+NP)=r, [NU+NP,NU+2NP)=c
__device__ int    g_deg3[NU_C + 2 * NP_C];
__device__ int    g_cur3[NU_C + 2 * NP_C];
__device__ float  g_inv3[NU_C + 2 * NP_C];
__device__ int    g_part[3 * 256];
__device__ int    g_rp_v[NU_C + 1];
__device__ int    g_rp_r[NP_C + 1];
__device__ int    g_rp_c[NP_C + 1];
__device__ int    g_ce_v[E_C];
__device__ int    g_ce_r[E_C];
__device__ int    g_ce_c[E_C];
// fp16 gather-source buffers (16 halves = 32B = 2 int4 per node); a = layer1, b = layer2
__device__ int4   g_h0a[NP_C * 2],  g_h0b[NP_C * 2];   // P src for visita gather
__device__ int4   g_h1a[NP_C * 2],  g_h1b[NP_C * 2];   // P src for conoce gather
__device__ int4   g_hu0a[NU_C * 2], g_hu0b[NU_C * 2];  // U src for rev gather
// fp32 self-term buffers
__device__ float4 g_b2a[NP_C * 4],  g_b2b[NP_C * 4];
__device__ float4 g_bu1a[NU_C * 4], g_bu1b[NU_C * 4];
// layer-1 activations (fp32)
__device__ float4 g_p1[NP_C * 4];
__device__ float4 g_u1[NU_C * 4];

// ---------------- fused CSR build ----------------
__global__ void __launch_bounds__(256)
count3_kernel(const int* __restrict__ dv, const int* __restrict__ dr,
              const int* __restrict__ dc, int e, int* __restrict__ deg3) {
    int i = blockIdx.x * blockDim.x + threadIdx.x;
    if (i >= e) return;
    int a = __ldg(&dv[i]);
    int b = __ldg(&dr[i]);
    int c = __ldg(&dc[i]);
    atomicAdd(&deg3[a], 1);
    atomicAdd(&deg3[NU_C + b], 1);
    atomicAdd(&deg3[NU_C + NP_C + c], 1);
}

__device__ __forceinline__ void seg_decode(int blk, int& seg, int& lb, int& base, int& n) {
    if (blk < NB_U)            { seg = 0; lb = blk;               base = 0;            n = NU_C; }
    else if (blk < NB_U + NB_P){ seg = 1; lb = blk - NB_U;        base = NU_C;         n = NP_C; }
    else                       { seg = 2; lb = blk - NB_U - NB_P; base = NU_C + NP_C;  n = NP_C; }
}

__global__ void scan_bs3(const int* __restrict__ deg3, int* __restrict__ part) {
    __shared__ int s[1024];
    int seg, lb, base, n;
    seg_decode(blockIdx.x, seg, lb, base, n);
    int tid = threadIdx.x;
    int i = lb * 1024 + tid;
    s[tid] = (i < n) ? deg3[base + i] : 0;
    __syncthreads();
    #pragma unroll
    for (int o = 512; o > 0; o >>= 1) {
        if (tid < o) s[tid] += s[tid + o];
        __syncthreads();
    }
    if (tid == 0) part[seg * 256 + lb] = s[0];
}

__global__ void scan_top3(int* __restrict__ part) {
    __shared__ int s[256];
    int seg = blockIdx.x;
    int nb = (seg == 0) ? NB_U : NB_P;
    int tid = threadIdx.x;
    int v = (tid < nb) ? part[seg * 256 + tid] : 0;
    s[tid] = v;
    __syncthreads();
    #pragma unroll
    for (int o = 1; o < 256; o <<= 1) {
        int t = (tid >= o) ? s[tid - o] : 0;
        __syncthreads();
        s[tid] += t;
        __syncthreads();
    }
    if (tid < nb) part[seg * 256 + tid] = s[tid] - v;   // exclusive
}

__global__ void scan_final3(const int* __restrict__ deg3, const int* __restrict__ part,
                            int* __restrict__ rp_v, int* __restrict__ rp_r,
                            int* __restrict__ rp_c, int* __restrict__ cur3,
                            float* __restrict__ inv3) {
    __shared__ int s[1024];
    int seg, lb, base, n;
    seg_decode(blockIdx.x, seg, lb, base, n);
    int* rp = (seg == 0) ? rp_v : (seg == 1) ? rp_r : rp_c;
    int tid = threadIdx.x;
    int i = lb * 1024 + tid;
    int v = (i < n) ? deg3[base + i] : 0;
    s[tid] = v;
    __syncthreads();
    #pragma unroll
    for (int o = 1; o < 1024; o <<= 1) {
        int t = (tid >= o) ? s[tid - o] : 0;
        __syncthreads();
        s[tid] += t;
        __syncthreads();
    }
    if (i < n) {
        int incl = part[seg * 256 + lb] + s[tid];
        rp[i + 1] = incl;
        cur3[base + i] = incl - v;
        inv3[base + i] = (v > 0) ? (1.0f / (float)v) : 0.f;
        if (i == 0) rp[0] = 0;
    }
}

__global__ void __launch_bounds__(256)
scatter3_kernel(const int* __restrict__ sv, const int* __restrict__ dv,
                const int* __restrict__ sr, const int* __restrict__ dr,
                const int* __restrict__ sc, const int* __restrict__ dc,
                int e, int* __restrict__ cur3,
                int* __restrict__ ce_v, int* __restrict__ ce_r, int* __restrict__ ce_c) {
    int i = blockIdx.x * blockDim.x + threadIdx.x;
    if (i >= e) return;
    int s0 = __ldg(&sv[i]); int d0 = __ldg(&dv[i]);
    int s1 = __ldg(&sr[i]); int d1 = __ldg(&dr[i]);
    int s2 = __ldg(&sc[i]); int d2 = __ldg(&dc[i]);
    int p0 = atomicAdd(&cur3[d0], 1);
    int p1 = atomicAdd(&cur3[NU_C + d1], 1);
    int p2 = atomicAdd(&cur3[NU_C + NP_C + d2], 1);
    ce_v[p0] = s0;
    ce_r[p1] = s1;
    ce_c[p2] = s2;
}

// ---------------- fused node transforms ----------------
// out[s][n,16] = x[n,F] @ (Wa[s] [+Wb[s]]) [+ ba[s]+bb[s]]
// HMASK bit s set -> out[s] stored as fp16 (gather source); else fp32 (self term).
struct TSlots {
    const float* Wa[3];
    const float* Wb[3];
    const float* ba[3];
    const float* bb[3];
    void*        out[3];
};

template <int F, int NS, int HMASK>
__global__ void __launch_bounds__(256)
transform_fused(const float* __restrict__ x, int n, TSlots t) {
    constexpr int R = 2;
    __shared__ float Ws[NS * F * 16];
    __shared__ float bs[NS * 16];
    int tid = threadIdx.x;
    for (int i = tid; i < NS * F * 16; i += 256) {
        int s = i / (F * 16);
        int j = i % (F * 16);
        float w = t.Wa[s][j];
        if (t.Wb[s]) w += t.Wb[s][j];
        Ws[i] = w;
    }
    if (tid < NS * 16) {
        int s = tid >> 4, c = tid & 15;
        float b = 0.f;
        if (t.ba[s]) b += t.ba[s][c];
        if (t.bb[s]) b += t.bb[s][c];
        bs[tid] = b;
    }
    __syncthreads();
    int base = blockIdx.x * (256 * R) + tid;
    int rows[R];
    float acc[R][NS * 16];
    #pragma unroll
    for (int rr = 0; rr < R; rr++) {
        rows[rr] = base + rr * 256;
        #pragma unroll
        for (int i = 0; i < NS * 16; i++) acc[rr][i] = bs[i];
    }
    #pragma unroll
    for (int k4 = 0; k4 < F / 4; k4++) {
        float4 v[R];
        #pragma unroll
        for (int rr = 0; rr < R; rr++)
            if (rows[rr] < n)
                v[rr] = __ldg(reinterpret_cast<const float4*>(x + (size_t)rows[rr] * F) + k4);
        #pragma unroll
        for (int s = 0; s < NS; s++) {
            const float* w0 = &Ws[(s * F + 4 * k4) * 16];
            #pragma unroll
            for (int c = 0; c < 16; c++) {
                float wa = w0[c], wb = w0[16 + c], wc = w0[32 + c], wd = w0[48 + c];
                #pragma unroll
                for (int rr = 0; rr < R; rr++) {
                    float a = acc[rr][s * 16 + c];
                    a = fmaf(v[rr].x, wa, a);
                    a = fmaf(v[rr].y, wb, a);
                    a = fmaf(v[rr].z, wc, a);
                    a = fmaf(v[rr].w, wd, a);
                    acc[rr][s * 16 + c] = a;
                }
            }
        }
    }
    #pragma unroll
    for (int rr = 0; rr < R; rr++) {
        if (rows[rr] >= n) continue;
        #pragma unroll
        for (int s = 0; s < NS; s++) {
            if (HMASK & (1 << s)) {
                __half2 h[8];
                #pragma unroll
                for (int q = 0; q < 8; q++)
                    h[q] = __floats2half2_rn(acc[rr][s * 16 + 2 * q],
                                             acc[rr][s * 16 + 2 * q + 1]);
                int4* o = (int4*)t.out[s] + (size_t)rows[rr] * 2;
                o[0] = *reinterpret_cast<int4*>(&h[0]);
                o[1] = *reinterpret_cast<int4*>(&h[4]);
            } else {
                float4* o = (float4*)t.out[s] + (size_t)rows[rr] * 4;
                #pragma unroll
                for (int q = 0; q < 4; q++)
                    o[q] = make_float4(acc[rr][s * 16 + 4 * q], acc[rr][s * 16 + 4 * q + 1],
                                       acc[rr][s * 16 + 4 * q + 2], acc[rr][s * 16 + 4 * q + 3]);
            }
        }
    }
}

// ---------------- fused gather: 2 lanes per node, zero shuffles, int2 index loads ----------------
__device__ __forceinline__ void acc8(float* a, int4 v) {
    float2 f0 = __half22float2(*reinterpret_cast<__half2*>(&v.x));
    float2 f1 = __half22float2(*reinterpret_cast<__half2*>(&v.y));
    float2 f2 = __half22float2(*reinterpret_cast<__half2*>(&v.z));
    float2 f3 = __half22float2(*reinterpret_cast<__half2*>(&v.w));
    a[0] += f0.x; a[1] += f0.y; a[2] += f1.x; a[3] += f1.y;
    a[4] += f2.x; a[5] += f2.y; a[6] += f3.x; a[7] += f3.y;
}

__device__ __forceinline__ void lane_gather(const int* __restrict__ rp,
                                            const int* __restrict__ ce,
                                            const int4* __restrict__ tsrc,
                                            int node, int q, float* a) {
    int beg = __ldg(&rp[node]), end = __ldg(&rp[node + 1]);
    int e = beg;
    if (e < end && (e & 1)) {            // align to int2 boundary
        acc8(a, __ldg(&tsrc[__ldg(&ce[e]) * 2 + q]));
        e++;
    }
    for (; e + 3 < end; e += 4) {        // 4 independent val loads in flight
        int2 c0 = __ldg(reinterpret_cast<const int2*>(ce + e));
        int2 c1 = __ldg(reinterpret_cast<const int2*>(ce + e + 2));
        int4 v0 = __ldg(&tsrc[c0.x * 2 + q]);
        int4 v1 = __ldg(&tsrc[c0.y * 2 + q]);
        int4 v2 = __ldg(&tsrc[c1.x * 2 + q]);
        int4 v3 = __ldg(&tsrc[c1.y * 2 + q]);
        acc8(a, v0); acc8(a, v1); acc8(a, v2); acc8(a, v3);
    }
    if (e + 1 < end) {
        int2 c0 = __ldg(reinterpret_cast<const int2*>(ce + e));
        acc8(a, __ldg(&tsrc[c0.x * 2 + q]));
        acc8(a, __ldg(&tsrc[c0.y * 2 + q]));
        e += 2;
    }
    if (e < end)
        acc8(a, __ldg(&tsrc[__ldg(&ce[e]) * 2 + q]));
}

__device__ __forceinline__ void store_node(float4* __restrict__ out, int node, int q,
                                           const float4* __restrict__ tself,
                                           const float* a, float inv,
                                           const float* b, float invB) {
    float4 s0 = __ldg(&tself[node * 4 + q * 2]);
    float4 s1 = __ldg(&tself[node * 4 + q * 2 + 1]);
    float4 o0, o1;
    o0.x = fmaf(a[0], inv, s0.x); o0.y = fmaf(a[1], inv, s0.y);
    o0.z = fmaf(a[2], inv, s0.z); o0.w = fmaf(a[3], inv, s0.w);
    o1.x = fmaf(a[4], inv, s1.x); o1.y = fmaf(a[5], inv, s1.y);
    o1.z = fmaf(a[6], inv, s1.z); o1.w = fmaf(a[7], inv, s1.w);
    if (b) {
        o0.x = fmaf(b[0], invB, o0.x); o0.y = fmaf(b[1], invB, o0.y);
        o0.z = fmaf(b[2], invB, o0.z); o0.w = fmaf(b[3], invB, o0.w);
        o1.x = fmaf(b[4], invB, o1.x); o1.y = fmaf(b[5], invB, o1.y);
        o1.z = fmaf(b[6], invB, o1.z); o1.w = fmaf(b[7], invB, o1.w);
    }
    o0.x = fmaxf(o0.x, 0.f); o0.y = fmaxf(o0.y, 0.f);
    o0.z = fmaxf(o0.z, 0.f); o0.w = fmaxf(o0.w, 0.f);
    o1.x = fmaxf(o1.x, 0.f); o1.y = fmaxf(o1.y, 0.f);
    o1.z = fmaxf(o1.z, 0.f); o1.w = fmaxf(o1.w, 0.f);
    out[node * 4 + q * 2] = o0;
    out[node * 4 + q * 2 + 1] = o1;
}

// One kernel does both node types for a layer: nodes [0,NU) = U (visita gather),
// nodes [NU, NU+NP) = P (rev + conoce gathers).
__global__ void __launch_bounds__(256)
gather_layer(const int* __restrict__ rp_v, const int* __restrict__ ce_v,
             const int4* __restrict__ srcV, const float4* __restrict__ selfU,
             float4* __restrict__ outU,
             const int* __restrict__ rp_r, const int* __restrict__ ce_r,
             const int4* __restrict__ srcR,
             const int* __restrict__ rp_c, const int* __restrict__ ce_c,
             const int4* __restrict__ srcC, const float4* __restrict__ selfP,
             float4* __restrict__ outP,
             const float* __restrict__ inv3, int nu, int np) {
    int gt = blockIdx.x * 256 + threadIdx.x;
    int node = gt >> 1;
    int q = gt & 1;
    if (node < nu) {
        float a[8] = {0.f, 0.f, 0.f, 0.f, 0.f, 0.f, 0.f, 0.f};
        lane_gather(rp_v, ce_v, srcV, node, q, a);
        store_node(outU, node, q, selfU, a, __ldg(&inv3[node]), nullptr, 0.f);
    } else if (node < nu + np) {
        int p = node - nu;
        float aR[8] = {0.f, 0.f, 0.f, 0.f, 0.f, 0.f, 0.f, 0.f};
        float aC[8] = {0.f, 0.f, 0.f, 0.f, 0.f, 0.f, 0.f, 0.f};
        lane_gather(rp_r, ce_r, srcR, p, q, aR);
        lane_gather(rp_c, ce_c, srcC, p, q, aC);
        store_node(outP, p, q, selfP, aR, __ldg(&inv3[nu + p]),
                   aC, __ldg(&inv3[nu + np + p]));
    }
}

// ---------------- host launcher ----------------
static inline void* sym_addr(const void* symbol) {
    void* p = nullptr;
    cudaGetSymbolAddress(&p, symbol);
    return p;
}

extern "C" void kernel_launch(void* const* d_in, const int* in_sizes, int n_in,
                              void* d_out, int out_size) {
    const float* xp = (const float*)d_in[0];
    const float* xu = (const float*)d_in[1];
    const int* ev_src = (const int*)d_in[2];
    const int* ev_dst = (const int*)d_in[3];
    const int* er_src = (const int*)d_in[4];
    const int* er_dst = (const int*)d_in[5];
    const int* ec_src = (const int*)d_in[6];
    const int* ec_dst = (const int*)d_in[7];
    const float* W1v_l = (const float*)d_in[8];
    const float* W1v_r = (const float*)d_in[9];
    const float* b1v   = (const float*)d_in[10];
    const float* W1r_l = (const float*)d_in[11];
    const float* W1r_r = (const float*)d_in[12];
    const float* b1r   = (const float*)d_in[13];
    const float* W1c_l = (const float*)d_in[14];
    const float* W1c_r = (const float*)d_in[15];
    const float* b1c   = (const float*)d_in[16];
    const float* W2v_l = (const float*)d_in[17];
    const float* W2v_r = (const float*)d_in[18];
    const float* b2v   = (const float*)d_in[19];
    const float* W2r_l = (const float*)d_in[20];
    const float* W2r_r = (const float*)d_in[21];
    const float* b2r   = (const float*)d_in[22];
    const float* W2c_l = (const float*)d_in[23];
    const float* W2c_r = (const float*)d_in[24];
    const float* b2c   = (const float*)d_in[25];

    const int NP = NP_C, NU = NU_C, E = E_C;

    int*    deg3 = (int*)sym_addr(g_deg3);
    int*    cur3 = (int*)sym_addr(g_cur3);
    float*  inv3 = (float*)sym_addr(g_inv3);
    int*    part = (int*)sym_addr(g_part);
    int*    rp_v = (int*)sym_addr(g_rp_v);
    int*    rp_r = (int*)sym_addr(g_rp_r);
    int*    rp_c = (int*)sym_addr(g_rp_c);
    int*    ce_v = (int*)sym_addr(g_ce_v);
    int*    ce_r = (int*)sym_addr(g_ce_r);
    int*    ce_c = (int*)sym_addr(g_ce_c);
    int4*   h0a  = (int4*)sym_addr(g_h0a);
    int4*   h0b  = (int4*)sym_addr(g_h0b);
    int4*   h1a  = (int4*)sym_addr(g_h1a);
    int4*   h1b  = (int4*)sym_addr(g_h1b);
    int4*   hu0a = (int4*)sym_addr(g_hu0a);
    int4*   hu0b = (int4*)sym_addr(g_hu0b);
    float4* b2a  = (float4*)sym_addr(g_b2a);
    float4* b2b  = (float4*)sym_addr(g_b2b);
    float4* bu1a = (float4*)sym_addr(g_bu1a);
    float4* bu1b = (float4*)sym_addr(g_bu1b);
    float4* p1   = (float4*)sym_addr(g_p1);
    float4* u1   = (float4*)sym_addr(g_u1);

    float4* out_p = (float4*)d_out;                              // [NP,16]
    float4* out_u = (float4*)((float*)d_out + (size_t)NP * 16);  // [NU,16]

    const int TB = 256;
    const int eb = (E + TB - 1) / TB;
    const int gP = (NP + 511) / 512;   // transform: 2 rows/thread
    const int gU = (NU + 511) / 512;
    const int gG = ((NU + NP) * 2 + TB - 1) / TB;   // fused gather grid

    // one-time host infra (streams/events; no device memory)
    static cudaStream_t s2 = nullptr;
    static cudaEvent_t evF = nullptr, evCSR = nullptr, evT = nullptr;
    static cudaEvent_t evG1 = nullptr, evT2 = nullptr;
    if (!s2) {
        cudaStreamCreateWithFlags(&s2, cudaStreamNonBlocking);
        cudaEventCreateWithFlags(&evF, cudaEventDisableTiming);
        cudaEventCreateWithFlags(&evCSR, cudaEventDisableTiming);
        cudaEventCreateWithFlags(&evT, cudaEventDisableTiming);
        cudaEventCreateWithFlags(&evG1, cudaEventDisableTiming);
        cudaEventCreateWithFlags(&evT2, cudaEventDisableTiming);
    }

    // ---- fork: CSR build (stream 0) || layer-1 transforms (s2) ----
    cudaEventRecord(evF, 0);
    cudaStreamWaitEvent(s2, evF, 0);

    cudaMemsetAsync(deg3, 0, (size_t)(NU + 2 * NP) * sizeof(int), 0);
    count3_kernel<<<eb, TB>>>(ev_dst, er_dst, ec_dst, E, deg3);
    scan_bs3<<<NB_TOT, 1024>>>(deg3, part);
    scan_top3<<<3, 256>>>(part);
    scan_final3<<<NB_TOT, 1024>>>(deg3, part, rp_v, rp_r, rp_c, cur3, inv3);
    scatter3_kernel<<<eb, TB>>>(ev_src, ev_dst, er_src, er_dst, ec_src, ec_dst,
                                E, cur3, ce_v, ce_r, ce_c);
    cudaEventRecord(evCSR, 0);

    {   // P transforms: h0a = xp@W1v_l (fp16); h1a = xp@W1c_l (fp16); b2a = xp@(W1r_r+W1c_r)+b1r+b1c
        TSlots t = {};
        t.Wa[0] = W1v_l;                     t.out[0] = h0a;
        t.Wa[1] = W1c_l;                     t.out[1] = h1a;
        t.Wa[2] = W1r_r; t.Wb[2] = W1c_r;
        t.ba[2] = b1r;   t.bb[2] = b1c;      t.out[2] = b2a;
        transform_fused<64, 3, 3><<<gP, TB, 0, s2>>>(xp, NP, t);
    }
    {   // U transforms: hu0a = xu@W1r_l (fp16); bu1a = xu@W1v_r + b1v
        TSlots t = {};
        t.Wa[0] = W1r_l;                     t.out[0] = hu0a;
        t.Wa[1] = W1v_r; t.ba[1] = b1v;      t.out[1] = bu1a;
        transform_fused<32, 2, 1><<<gU, TB, 0, s2>>>(xu, NU, t);
    }
    cudaEventRecord(evT, s2);

    // ---- join: layer-1 gather needs CSR + transforms ----
    cudaStreamWaitEvent(0, evT, 0);
    gather_layer<<<gG, TB>>>(rp_v, ce_v, h0a, bu1a, u1,
                             rp_r, ce_r, hu0a, rp_c, ce_c, h1a, b2a, p1,
                             inv3, NU, NP);
    cudaEventRecord(evG1, 0);
    cudaStreamWaitEvent(s2, evG1, 0);

    // ---- layer-2 transforms: P on stream 0, U on s2 (concurrent) ----
    {   // P transforms: h0b = p1@W2v_l ; h1b = p1@W2c_l ; b2b = p1@(W2r_r+W2c_r)+b2r+b2c
        TSlots t = {};
        t.Wa[0] = W2v_l;                     t.out[0] = h0b;
        t.Wa[1] = W2c_l;                     t.out[1] = h1b;
        t.Wa[2] = W2r_r; t.Wb[2] = W2c_r;
        t.ba[2] = b2r;   t.bb[2] = b2c;      t.out[2] = b2b;
        transform_fused<16, 3, 3><<<gP, TB>>>((const float*)p1, NP, t);
    }
    {   // U transforms: hu0b = u1@W2r_l ; bu1b = u1@W2v_r + b2v
        TSlots t = {};
        t.Wa[0] = W2r_l;                     t.out[0] = hu0b;
        t.Wa[1] = W2v_r; t.ba[1] = b2v;      t.out[1] = bu1b;
        transform_fused<16, 2, 1><<<gU, TB, 0, s2>>>((const float*)u1, NU, t);
    }
    cudaEventRecord(evT2, s2);
    cudaStreamWaitEvent(0, evT2, 0);

    // ---- layer-2 gather ----
    gather_layer<<<gG, TB>>>(rp_v, ce_v, h0b, bu1b, out_u,
                             rp_r, ce_r, hu0b, rp_c, ce_c, h1b, b2b, out_p,
                             inv3, NU, NP);
}